// round 5
// baseline (speedup 1.0000x reference)
#include <cuda_runtime.h>
#include <cuda_bf16.h>
#include <mma.h>
#include <math.h>

using namespace nvcuda;

#define B_   2
#define S_   2048
#define H_   1024
#define NH_  16
#define HD_  64
#define MR_  (B_ * S_)
#define ATTN_SCALE 0.125f

// ---------------- scratch ----------------------------------------------------
__device__ float g_q[B_ * NH_ * S_ * HD_];   // (b,h,s,d)  tf32-rounded, q pre-scaled
__device__ float g_k[B_ * NH_ * S_ * HD_];
__device__ float g_v[B_ * NH_ * S_ * HD_];
__device__ float g_att[MR_ * H_];            // (b,s,H)    tf32-rounded
__device__ float g_x_t[MR_ * H_];            // tf32-rounded x
__device__ float g_wqkv_t[H_ * 3 * H_];      // tf32-rounded w_qkv
__device__ float g_wout_t[H_ * H_];          // tf32-rounded w_out

// ---------------- cp.async helpers ------------------------------------------
__device__ __forceinline__ unsigned smem_u32(const void* p) {
    return (unsigned)__cvta_generic_to_shared(p);
}
#define CP_ASYNC16(dst_u32, src_ptr) \
    asm volatile("cp.async.cg.shared.global [%0], [%1], 16;\n" :: "r"(dst_u32), "l"(src_ptr))
#define CP_COMMIT() asm volatile("cp.async.commit_group;\n" ::)
#define CP_WAIT(N)  asm volatile("cp.async.wait_group %0;\n" :: "n"(N))

// ---------------- prep: round fp32 -> tf32 into device-global scratch --------
template <int DST>
__global__ void round_tf32_kernel(const float4* __restrict__ src, int n4)
{
    float4* dst = (DST == 0) ? (float4*)g_x_t
                : (DST == 1) ? (float4*)g_wqkv_t
                             : (float4*)g_wout_t;
    int i = blockIdx.x * blockDim.x + threadIdx.x;
    if (i < n4) {
        float4 v = src[i];
        v.x = wmma::__float_to_tf32(v.x);
        v.y = wmma::__float_to_tf32(v.y);
        v.z = wmma::__float_to_tf32(v.z);
        v.w = wmma::__float_to_tf32(v.w);
        dst[i] = v;
    }
}

// ---------------- tf32 wmma GEMM, cp.async 2-stage, ONE sync/iter ------------
#define BM 128
#define BN 128
#define BK 32
#define LDA_S 40
#define LDB_S 136
#define A_STAGE (BM * LDA_S)
#define B_STAGE (BK * LDB_S)
#define GEMM_SMEM ((2 * A_STAGE + 2 * B_STAGE) * 4)

template <int EPI>
__global__ __launch_bounds__(256) void gemm_tf32_kernel(
    const float* __restrict__ bias, float* __restrict__ C,
    int M, int N, int K)
{
    const float* A  = (EPI == 1) ? (const float*)g_att    : (const float*)g_x_t;
    const float* Bw = (EPI == 1) ? (const float*)g_wout_t : (const float*)g_wqkv_t;

    extern __shared__ float sm[];
    float* As = sm;                    // [2][BM][LDA_S]
    float* Bs = sm + 2 * A_STAGE;      // [2][BK][LDB_S]

    const int bm   = blockIdx.y * BM;
    const int bn   = blockIdx.x * BN;
    const int tid  = threadIdx.x;
    const int warp = tid >> 5;
    const int lane = tid & 31;
    const int wm   = warp >> 2;
    const int wn   = warp & 3;

    wmma::fragment<wmma::accumulator, 16, 16, 8, float> acc[4][2];
#pragma unroll
    for (int i = 0; i < 4; i++)
#pragma unroll
        for (int j = 0; j < 2; j++) wmma::fill_fragment(acc[i][j], 0.0f);

    const int NIT = K / BK;

    auto load_stage = [&](int st, int k0) {
#pragma unroll
        for (int it = 0; it < 4; it++) {
            int f4 = tid + it * 256;
            int r  = f4 >> 3;
            int c4 = (f4 & 7) << 2;
            CP_ASYNC16(smem_u32(&As[st * A_STAGE + r * LDA_S + c4]),
                       &A[(size_t)(bm + r) * K + k0 + c4]);
        }
#pragma unroll
        for (int it = 0; it < 4; it++) {
            int f4 = tid + it * 256;
            int r  = f4 >> 5;
            int c4 = (f4 & 31) << 2;
            CP_ASYNC16(smem_u32(&Bs[st * B_STAGE + r * LDB_S + c4]),
                       &Bw[(size_t)(k0 + r) * N + bn + c4]);
        }
    };

    load_stage(0, 0);
    CP_COMMIT();

    for (int it = 0; it < NIT; it++) {
        CP_WAIT(0);
        __syncthreads();                       // stage `it` visible; slot (it+1)&1 free
        if (it + 1 < NIT) {
            load_stage((it + 1) & 1, (it + 1) * BK);   // overlaps compute below
            CP_COMMIT();
        }
        const float* Ac = &As[(it & 1) * A_STAGE];
        const float* Bc = &Bs[(it & 1) * B_STAGE];
#pragma unroll
        for (int kk = 0; kk < BK / 8; kk++) {
            wmma::fragment<wmma::matrix_a, 16, 16, 8, wmma::precision::tf32, wmma::row_major> af[4];
            wmma::fragment<wmma::matrix_b, 16, 16, 8, wmma::precision::tf32, wmma::row_major> bf[2];
#pragma unroll
            for (int i = 0; i < 4; i++)
                wmma::load_matrix_sync(af[i], &Ac[(wm * 64 + i * 16) * LDA_S + kk * 8], LDA_S);
#pragma unroll
            for (int j = 0; j < 2; j++)
                wmma::load_matrix_sync(bf[j], &Bc[(kk * 8) * LDB_S + wn * 32 + j * 16], LDB_S);
#pragma unroll
            for (int i = 0; i < 4; i++)
#pragma unroll
                for (int j = 0; j < 2; j++)
                    wmma::mma_sync(acc[i][j], af[i], bf[j], acc[i][j]);
        }
    }
    __syncthreads();    // all compute done before As reused as scratch

    float* scr = &As[warp * 16 * 20];
#pragma unroll
    for (int i = 0; i < 4; i++) {
#pragma unroll
        for (int j = 0; j < 2; j++) {
            wmma::store_matrix_sync(scr, acc[i][j], 20, wmma::mem_row_major);
            __syncwarp();
#pragma unroll
            for (int e = 0; e < 8; e++) {
                int idx = lane + e * 32;
                int rr = idx >> 4, cc = idx & 15;
                int m = bm + wm * 64 + i * 16 + rr;
                int n = bn + wn * 32 + j * 16 + cc;
                float val = scr[rr * 20 + cc] + bias[n];
                if (EPI == 0) {
                    int which = n >> 10;           // 0=q 1=k 2=v
                    int hn = n & (H_ - 1);
                    int h  = hn >> 6;
                    int d  = hn & (HD_ - 1);
                    int bb = m >> 11;
                    int s  = m & (S_ - 1);
                    if (which == 0) val *= ATTN_SCALE;
                    val = wmma::__float_to_tf32(val);
                    size_t dst = ((size_t)(bb * NH_ + h) * S_ + s) * HD_ + d;
                    float* T = (which == 0) ? g_q : (which == 1) ? g_k : g_v;
                    T[dst] = val;
                } else {
                    C[(size_t)m * N + n] = val;
                }
            }
            __syncwarp();
        }
    }
}

// ---------------- attention: warp-private softmax ----------------------------
// 128-query blocks, 8 warps; warp w owns rows [w*16, w*16+16) x ALL 64 keys of
// each key tile. S-store/exp/P-load are warp-private (syncwarp only); the ONLY
// block sync per key tile guards the double-buffered K/V stages.
// Mask: allow j >= i. Key tiles start at 2*qt. Tiles i>=2 are mask-free.
// Warps 4..7 skip tile i==0 entirely (fully masked for their rows).
#define QT_ROWS 128
#define KT_ 64
#define LDS_T 72
#define KV_STAGE (KT_ * LDS_T)        // 4608 floats
#define SS_W (16 * LDS_T)             // 1152 floats per warp
#define ATTN_SMEM ((4 * KV_STAGE + 8 * SS_W) * 4)   // ~108 KB

__global__ __launch_bounds__(256) void attn_tf32_kernel()
{
    extern __shared__ float sm[];
    float* Ks = sm;                    // [2][KT_][LDS_T]
    float* Vs = sm + 2 * KV_STAGE;     // [2][KT_][LDS_T]
    float* Sw = sm + 4 * KV_STAGE;     // [8][16][LDS_T] warp-private strips

    const int qt = blockIdx.x;         // 0..15  (128-row query tiles)
    const int bh = blockIdx.y;
    const float* Qb = g_q + (size_t)bh * S_ * HD_;
    const float* Kb = g_k + (size_t)bh * S_ * HD_;
    const float* Vb = g_v + (size_t)bh * S_ * HD_;

    const int tid  = threadIdx.x;
    const int warp = tid >> 5;
    const int lane = tid & 31;
    float* Ss = &Sw[warp * SS_W];

    const int r0   = qt * QT_ROWS + warp * 16;   // first global row of this warp
    const int lrow = lane >> 1;                   // 0..15 row within warp strip
    const int lc0  = (lane & 1) * 32;             // col half 0/32

    auto load_kv = [&](int st, int kt) {
#pragma unroll
        for (int it = 0; it < 4; it++) {
            int f4 = tid + it * 256;               // 0..1023
            int r  = f4 >> 4;
            int c4 = (f4 & 15) << 2;
            size_t src = (size_t)(kt * KT_ + r) * HD_ + c4;
            CP_ASYNC16(smem_u32(&Ks[st * KV_STAGE + r * LDS_T + c4]), &Kb[src]);
            CP_ASYNC16(smem_u32(&Vs[st * KV_STAGE + r * LDS_T + c4]), &Vb[src]);
        }
    };

    const int kt0 = 2 * qt;
    const int nkt = S_ / KT_ - kt0;    // 32 - 2*qt >= 2

    load_kv(0, kt0);
    CP_COMMIT();

    // stage this warp's Q rows into its private strip, then build fragments
    {
#pragma unroll
        for (int f = 0; f < 8; f++) {
            *reinterpret_cast<float4*>(&Ss[lrow * LDS_T + lc0 + f * 4]) =
                *reinterpret_cast<const float4*>(&Qb[(size_t)(r0 + lrow) * HD_ + lc0 + f * 4]);
        }
        __syncwarp();
    }
    wmma::fragment<wmma::matrix_a, 16, 16, 8, wmma::precision::tf32, wmma::row_major> qf[8];
#pragma unroll
    for (int kk = 0; kk < 8; kk++)
        wmma::load_matrix_sync(qf[kk], &Ss[kk * 8], LDS_T);
    __syncwarp();

    wmma::fragment<wmma::accumulator, 16, 16, 8, float> o_acc[4];
#pragma unroll
    for (int j = 0; j < 4; j++) wmma::fill_fragment(o_acc[j], 0.0f);

    float l_sum[16 / 16];   // per-thread: one row (lrow), accumulated full-row sum
    l_sum[0] = 0.0f;

    for (int i = 0; i < nkt; i++) {
        const int kt = kt0 + i;
        CP_WAIT(0);
        __syncthreads();                 // KV stage i ready; slot (i+1)&1 free
        if (i + 1 < nkt) {
            load_kv((i + 1) & 1, kt + 1);
            CP_COMMIT();
        }
        const float* Kc = &Ks[(i & 1) * KV_STAGE];
        const float* Vc = &Vs[(i & 1) * KV_STAGE];

        // fully-masked tile for this warp? (max key < min row)
        if (kt * KT_ + KT_ - 1 < r0) continue;

        // S = Q @ K^T   (16 x 64)
        wmma::fragment<wmma::accumulator, 16, 16, 8, float> s_acc[4];
#pragma unroll
        for (int j = 0; j < 4; j++) wmma::fill_fragment(s_acc[j], 0.0f);
#pragma unroll
        for (int kk = 0; kk < 8; kk++) {
            wmma::fragment<wmma::matrix_b, 16, 16, 8, wmma::precision::tf32, wmma::col_major> kf;
#pragma unroll
            for (int j = 0; j < 4; j++) {
                wmma::load_matrix_sync(kf, &Kc[(j * 16) * LDS_T + kk * 8], LDS_T);
                wmma::mma_sync(s_acc[j], qf[kk], kf, s_acc[j]);
            }
        }
#pragma unroll
        for (int j = 0; j < 4; j++)
            wmma::store_matrix_sync(&Ss[j * 16], s_acc[j], LDS_T, wmma::mem_row_major);
        __syncwarp();

        // exp (+ mask on first two tiles) + row sums  — warp-private
        {
            float part = 0.0f;
            if (i < 2) {
                int grow = r0 + lrow;
#pragma unroll
                for (int c = 0; c < 32; c++) {
                    int gcol = kt * KT_ + lc0 + c;
                    float s = Ss[lrow * LDS_T + lc0 + c];
                    float p = (gcol >= grow) ? __expf(s) : 0.0f;
                    p = wmma::__float_to_tf32(p);
                    Ss[lrow * LDS_T + lc0 + c] = p;
                    part += p;
                }
            } else {
#pragma unroll
                for (int c = 0; c < 32; c++) {
                    float p = __expf(Ss[lrow * LDS_T + lc0 + c]);
                    p = wmma::__float_to_tf32(p);
                    Ss[lrow * LDS_T + lc0 + c] = p;
                    part += p;
                }
            }
            part += __shfl_xor_sync(0xffffffffu, part, 1);   // combine col halves
            l_sum[0] += part;
        }
        __syncwarp();

        // O += P @ V   (16 x 64)
#pragma unroll
        for (int kk = 0; kk < 8; kk++) {
            wmma::fragment<wmma::matrix_a, 16, 16, 8, wmma::precision::tf32, wmma::row_major> pf;
            wmma::load_matrix_sync(pf, &Ss[kk * 8], LDS_T);
#pragma unroll
            for (int j = 0; j < 4; j++) {
                wmma::fragment<wmma::matrix_b, 16, 16, 8, wmma::precision::tf32, wmma::row_major> vf;
                wmma::load_matrix_sync(vf, &Vc[(kk * 8) * LDS_T + j * 16], LDS_T);
                wmma::mma_sync(o_acc[j], pf, vf, o_acc[j]);
            }
        }
        __syncwarp();   // Ss consumed before next tile's S store
    }

    // write O / l  -> g_att (b, s, H), tf32-rounded
#pragma unroll
    for (int j = 0; j < 4; j++)
        wmma::store_matrix_sync(&Ss[j * 16], o_acc[j], LDS_T, wmma::mem_row_major);
    __syncwarp();
    {
        int grow = r0 + lrow;
        int bb = bh >> 4, h = bh & 15;
        float inv_l = 1.0f / l_sum[0];
        size_t base = ((size_t)bb * S_ + grow) * H_ + h * HD_ + lc0;
#pragma unroll
        for (int c = 0; c < 32; c++)
            g_att[base + c] = wmma::__float_to_tf32(Ss[lrow * LDS_T + lc0 + c] * inv_l);
    }
}

// ---------------- launch -----------------------------------------------------
extern "C" void kernel_launch(void* const* d_in, const int* in_sizes, int n_in,
                              void* d_out, int out_size)
{
    const float* x     = (const float*)d_in[0];
    const float* w_qkv = (const float*)d_in[1];
    const float* b_qkv = (const float*)d_in[2];
    const float* w_out = (const float*)d_in[3];
    const float* b_out = (const float*)d_in[4];
    float* out = (float*)d_out;

    cudaFuncSetAttribute(gemm_tf32_kernel<0>,
                         cudaFuncAttributeMaxDynamicSharedMemorySize, GEMM_SMEM);
    cudaFuncSetAttribute(gemm_tf32_kernel<1>,
                         cudaFuncAttributeMaxDynamicSharedMemorySize, GEMM_SMEM);
    cudaFuncSetAttribute(attn_tf32_kernel,
                         cudaFuncAttributeMaxDynamicSharedMemorySize, ATTN_SMEM);

    round_tf32_kernel<0><<<(MR_ * H_ / 4 + 255) / 256, 256>>>((const float4*)x, MR_ * H_ / 4);
    round_tf32_kernel<1><<<(H_ * 3 * H_ / 4 + 255) / 256, 256>>>((const float4*)w_qkv, H_ * 3 * H_ / 4);
    round_tf32_kernel<2><<<(H_ * H_ / 4 + 255) / 256, 256>>>((const float4*)w_out, H_ * H_ / 4);

    dim3 g1((3 * H_) / BN, MR_ / BM);
    gemm_tf32_kernel<0><<<g1, 256, GEMM_SMEM>>>(b_qkv, nullptr, MR_, 3 * H_, H_);

    dim3 g2(S_ / QT_ROWS, B_ * NH_);
    attn_tf32_kernel<<<g2, 256, ATTN_SMEM>>>();

    dim3 g3(H_ / BN, MR_ / BM);
    gemm_tf32_kernel<1><<<g3, 256, GEMM_SMEM>>>(b_out, out, MR_, H_, H_);
}

// round 7
// speedup vs baseline: 1.0121x; 1.0121x over previous
#include <cuda_runtime.h>
#include <cuda_bf16.h>
#include <mma.h>
#include <math.h>

using namespace nvcuda;

#define B_   2
#define S_   2048
#define H_   1024
#define NH_  16
#define HD_  64
#define MR_  (B_ * S_)
#define ATTN_SCALE 0.125f

// ---------------- scratch ----------------------------------------------------
__device__ float g_q[B_ * NH_ * S_ * HD_];   // (b,h,s,d)  tf32-rounded, q pre-scaled
__device__ float g_k[B_ * NH_ * S_ * HD_];
__device__ float g_v[B_ * NH_ * S_ * HD_];
__device__ float g_att[MR_ * H_];            // (b,s,H)    tf32-rounded
__device__ float g_x_t[MR_ * H_];            // tf32-rounded x
__device__ float g_wqkv_t[H_ * 3 * H_];      // tf32-rounded w_qkv
__device__ float g_wout_t[H_ * H_];          // tf32-rounded w_out

// ---------------- cp.async helpers ------------------------------------------
__device__ __forceinline__ unsigned smem_u32(const void* p) {
    return (unsigned)__cvta_generic_to_shared(p);
}
#define CP_ASYNC16(dst_u32, src_ptr) \
    asm volatile("cp.async.cg.shared.global [%0], [%1], 16;\n" :: "r"(dst_u32), "l"(src_ptr))
#define CP_COMMIT() asm volatile("cp.async.commit_group;\n" ::)
#define CP_WAIT(N)  asm volatile("cp.async.wait_group %0;\n" :: "n"(N))

// ---------------- prep: round fp32 -> tf32 into device-global scratch --------
template <int DST>
__global__ void round_tf32_kernel(const float4* __restrict__ src, int n4)
{
    float4* dst = (DST == 0) ? (float4*)g_x_t
                : (DST == 1) ? (float4*)g_wqkv_t
                             : (float4*)g_wout_t;
    int i = blockIdx.x * blockDim.x + threadIdx.x;
    if (i < n4) {
        float4 v = src[i];
        v.x = wmma::__float_to_tf32(v.x);
        v.y = wmma::__float_to_tf32(v.y);
        v.z = wmma::__float_to_tf32(v.z);
        v.w = wmma::__float_to_tf32(v.w);
        dst[i] = v;
    }
}

// ---------------- tf32 wmma GEMM, cp.async 3-stage, one sync/iter ------------
#define BM 128
#define BN 128
#define BK 32
#define LDA_S 40
#define LDB_S 132
#define A_STAGE (BM * LDA_S)     // 5120 floats
#define B_STAGE (BK * LDB_S)     // 4224 floats
#define GEMM_SMEM ((3 * A_STAGE + 3 * B_STAGE) * 4)   // ~110 KB

template <int EPI>
__global__ __launch_bounds__(256) void gemm_tf32_kernel(
    const float* __restrict__ bias, float* __restrict__ C,
    int M, int N, int K)
{
    const float* A  = (EPI == 1) ? (const float*)g_att    : (const float*)g_x_t;
    const float* Bw = (EPI == 1) ? (const float*)g_wout_t : (const float*)g_wqkv_t;

    extern __shared__ float sm[];
    float* As = sm;                    // [3][BM][LDA_S]
    float* Bs = sm + 3 * A_STAGE;      // [3][BK][LDB_S]

    const int bm   = blockIdx.y * BM;
    const int bn   = blockIdx.x * BN;
    const int tid  = threadIdx.x;
    const int warp = tid >> 5;
    const int lane = tid & 31;
    const int wm   = warp >> 2;
    const int wn   = warp & 3;

    wmma::fragment<wmma::accumulator, 16, 16, 8, float> acc[4][2];
#pragma unroll
    for (int i = 0; i < 4; i++)
#pragma unroll
        for (int j = 0; j < 2; j++) wmma::fill_fragment(acc[i][j], 0.0f);

    const int NIT = K / BK;

    auto load_stage = [&](int st, int k0) {
#pragma unroll
        for (int it = 0; it < 4; it++) {
            int f4 = tid + it * 256;
            int r  = f4 >> 3;
            int c4 = (f4 & 7) << 2;
            CP_ASYNC16(smem_u32(&As[st * A_STAGE + r * LDA_S + c4]),
                       &A[(size_t)(bm + r) * K + k0 + c4]);
        }
#pragma unroll
        for (int it = 0; it < 4; it++) {
            int f4 = tid + it * 256;
            int r  = f4 >> 5;
            int c4 = (f4 & 31) << 2;
            CP_ASYNC16(smem_u32(&Bs[st * B_STAGE + r * LDB_S + c4]),
                       &Bw[(size_t)(k0 + r) * N + bn + c4]);
        }
    };

    load_stage(0, 0);
    CP_COMMIT();
    load_stage(1, BK);
    CP_COMMIT();

    int st_c = 0;   // compute stage
    int st_l = 2;   // next load stage
    for (int it = 0; it < NIT; it++) {
        if (it + 1 < NIT) { CP_WAIT(1); } else { CP_WAIT(0); }
        __syncthreads();                     // stage it visible; slot st_l free
        if (it + 2 < NIT) {
            load_stage(st_l, (it + 2) * BK); // overlaps compute below
            CP_COMMIT();
        }
        const float* Ac = &As[st_c * A_STAGE];
        const float* Bc = &Bs[st_c * B_STAGE];
#pragma unroll
        for (int kk = 0; kk < BK / 8; kk++) {
            wmma::fragment<wmma::matrix_a, 16, 16, 8, wmma::precision::tf32, wmma::row_major> af[4];
            wmma::fragment<wmma::matrix_b, 16, 16, 8, wmma::precision::tf32, wmma::row_major> bf[2];
#pragma unroll
            for (int i = 0; i < 4; i++)
                wmma::load_matrix_sync(af[i], &Ac[(wm * 64 + i * 16) * LDA_S + kk * 8], LDA_S);
#pragma unroll
            for (int j = 0; j < 2; j++)
                wmma::load_matrix_sync(bf[j], &Bc[(kk * 8) * LDB_S + wn * 32 + j * 16], LDB_S);
#pragma unroll
            for (int i = 0; i < 4; i++)
#pragma unroll
                for (int j = 0; j < 2; j++)
                    wmma::mma_sync(acc[i][j], af[i], bf[j], acc[i][j]);
        }
        st_c = (st_c == 2) ? 0 : st_c + 1;
        st_l = (st_l == 2) ? 0 : st_l + 1;
    }
    __syncthreads();    // all compute done before As reused as scratch

    float* scr = &As[warp * 16 * 20];
#pragma unroll
    for (int i = 0; i < 4; i++) {
#pragma unroll
        for (int j = 0; j < 2; j++) {
            wmma::store_matrix_sync(scr, acc[i][j], 20, wmma::mem_row_major);
            __syncwarp();
#pragma unroll
            for (int e = 0; e < 8; e++) {
                int idx = lane + e * 32;
                int rr = idx >> 4, cc = idx & 15;
                int m = bm + wm * 64 + i * 16 + rr;
                int n = bn + wn * 32 + j * 16 + cc;
                float val = scr[rr * 20 + cc] + bias[n];
                if (EPI == 0) {
                    int which = n >> 10;           // 0=q 1=k 2=v
                    int hn = n & (H_ - 1);
                    int h  = hn >> 6;
                    int d  = hn & (HD_ - 1);
                    int bb = m >> 11;
                    int s  = m & (S_ - 1);
                    if (which == 0) val *= ATTN_SCALE;
                    val = wmma::__float_to_tf32(val);
                    size_t dst = ((size_t)(bb * NH_ + h) * S_ + s) * HD_ + d;
                    float* T = (which == 0) ? g_q : (which == 1) ? g_k : g_v;
                    T[dst] = val;
                } else {
                    C[(size_t)m * N + n] = val;
                }
            }
            __syncwarp();
        }
    }
}

// ---------------- tf32 wmma attention (mask: allow j >= i) -------------------
// Block-wide 64x64 tiles (R4 layout), 8 warps: wr=warp>>1 rows, wc=warp&1 cols.
// Loop reordered: prefetch issued AFTER the top barrier, so the old
// end-of-loop barrier is redundant -> 3 syncs per key tile instead of 4.
#define LDS_T 72
#define KV_STAGE (64 * LDS_T)
#define ATTN_SMEM ((4 * KV_STAGE + KV_STAGE + 64) * 4)

__global__ __launch_bounds__(256) void attn_tf32_kernel()
{
    extern __shared__ float sm[];
    float* Ks  = sm;                   // [2][64][LDS_T]
    float* Vs  = sm + 2 * KV_STAGE;    // [2][64][LDS_T]
    float* Ss  = sm + 4 * KV_STAGE;    // [64][LDS_T]
    float* l_s = sm + 5 * KV_STAGE;    // [64]

    const int qt = blockIdx.x;
    const int bh = blockIdx.y;
    const float* Qb = g_q + (size_t)bh * S_ * HD_;
    const float* Kb = g_k + (size_t)bh * S_ * HD_;
    const float* Vb = g_v + (size_t)bh * S_ * HD_;

    const int tid  = threadIdx.x;
    const int warp = tid >> 5;
    const int wr   = warp >> 1;
    const int wc   = warp & 1;

    auto load_kv = [&](int st, int kt) {
#pragma unroll
        for (int it = 0; it < 4; it++) {
            int f4 = tid + it * 256;
            int r  = f4 >> 4;
            int c4 = (f4 & 15) << 2;
            size_t src = (size_t)(kt * 64 + r) * HD_ + c4;
            CP_ASYNC16(smem_u32(&Ks[st * KV_STAGE + r * LDS_T + c4]), &Kb[src]);
            CP_ASYNC16(smem_u32(&Vs[st * KV_STAGE + r * LDS_T + c4]), &Vb[src]);
        }
    };

    const int nkt = S_ / 64 - qt;
    load_kv(0, qt);
    CP_COMMIT();

    // stage Q into Ss (already scaled + rounded)
    for (int idx = tid; idx < 64 * HD_; idx += 256) {
        int r = idx >> 6, c = idx & 63;
        Ss[r * LDS_T + c] = Qb[(size_t)(qt * 64 + r) * HD_ + c];
    }
    if (tid < 64) l_s[tid] = 0.0f;
    __syncthreads();                        // Q staged before qf loads

    wmma::fragment<wmma::matrix_a, 16, 16, 8, wmma::precision::tf32, wmma::row_major> qf[8];
#pragma unroll
    for (int kk = 0; kk < 8; kk++)
        wmma::load_matrix_sync(qf[kk], &Ss[(wr * 16) * LDS_T + kk * 8], LDS_T);

    wmma::fragment<wmma::accumulator, 16, 16, 8, float> o_acc[2];
    wmma::fill_fragment(o_acc[0], 0.0f);
    wmma::fill_fragment(o_acc[1], 0.0f);
    // NOTE: first in-loop sync [A] orders qf loads (all warps) before Ss reuse.

    for (int i = 0; i < nkt; i++) {
        const int kt = qt + i;
        CP_WAIT(0);
        __syncthreads();                    // [A] KV stage i visible; other slot free
        if (i + 1 < nkt) {
            load_kv((i + 1) & 1, kt + 1);   // overlaps this tile's compute
            CP_COMMIT();
        }
        const float* Kc = &Ks[(i & 1) * KV_STAGE];
        const float* Vc = &Vs[(i & 1) * KV_STAGE];

        // S = Q @ K^T
        wmma::fragment<wmma::accumulator, 16, 16, 8, float> s_acc[2];
        wmma::fill_fragment(s_acc[0], 0.0f);
        wmma::fill_fragment(s_acc[1], 0.0f);
#pragma unroll
        for (int kk = 0; kk < 8; kk++) {
            wmma::fragment<wmma::matrix_b, 16, 16, 8, wmma::precision::tf32, wmma::col_major> kf[2];
#pragma unroll
            for (int j = 0; j < 2; j++)
                wmma::load_matrix_sync(kf[j], &Kc[(wc * 32 + j * 16) * LDS_T + kk * 8], LDS_T);
            wmma::mma_sync(s_acc[0], qf[kk], kf[0], s_acc[0]);
            wmma::mma_sync(s_acc[1], qf[kk], kf[1], s_acc[1]);
        }
        wmma::store_matrix_sync(&Ss[(wr * 16) * LDS_T + wc * 32],      s_acc[0], LDS_T, wmma::mem_row_major);
        wmma::store_matrix_sync(&Ss[(wr * 16) * LDS_T + wc * 32 + 16], s_acc[1], LDS_T, wmma::mem_row_major);
        __syncthreads();                    // [B] S visible to exp pass

        // exp (+ mask on diagonal tile only) + row-sum; store tf32-rounded P
        {
            int row  = tid >> 2;
            int col0 = (tid & 3) << 4;
            float part = 0.0f;
            if (i == 0) {
                int grow = qt * 64 + row;
#pragma unroll
                for (int c = 0; c < 16; c++) {
                    int gcol = kt * 64 + col0 + c;
                    float s = Ss[row * LDS_T + col0 + c];
                    float p = (gcol >= grow) ? __expf(s) : 0.0f;
                    p = wmma::__float_to_tf32(p);
                    Ss[row * LDS_T + col0 + c] = p;
                    part += p;
                }
            } else {
#pragma unroll
                for (int c = 0; c < 16; c++) {
                    float p = __expf(Ss[row * LDS_T + col0 + c]);
                    p = wmma::__float_to_tf32(p);
                    Ss[row * LDS_T + col0 + c] = p;
                    part += p;
                }
            }
            part += __shfl_xor_sync(0xffffffffu, part, 1);
            part += __shfl_xor_sync(0xffffffffu, part, 2);
            if ((tid & 3) == 0) l_s[row] += part;
        }
        __syncthreads();                    // [C] P visible to PV mma

        // O += P @ V   (no end-of-loop sync: next iter's [A] covers the hazard)
#pragma unroll
        for (int kk = 0; kk < 8; kk++) {
            wmma::fragment<wmma::matrix_a, 16, 16, 8, wmma::precision::tf32, wmma::row_major> pf;
            wmma::load_matrix_sync(pf, &Ss[(wr * 16) * LDS_T + kk * 8], LDS_T);
            wmma::fragment<wmma::matrix_b, 16, 16, 8, wmma::precision::tf32, wmma::row_major> vf[2];
#pragma unroll
            for (int j = 0; j < 2; j++)
                wmma::load_matrix_sync(vf[j], &Vc[(kk * 8) * LDS_T + wc * 32 + j * 16], LDS_T);
            wmma::mma_sync(o_acc[0], pf, vf[0], o_acc[0]);
            wmma::mma_sync(o_acc[1], pf, vf[1], o_acc[1]);
        }
    }
    __syncthreads();   // all PV reads of Ss done before o_acc stores reuse it

    // O / l -> g_att (b, s, H), tf32-rounded
    wmma::store_matrix_sync(&Ss[(wr * 16) * LDS_T + wc * 32],      o_acc[0], LDS_T, wmma::mem_row_major);
    wmma::store_matrix_sync(&Ss[(wr * 16) * LDS_T + wc * 32 + 16], o_acc[1], LDS_T, wmma::mem_row_major);
    __syncthreads();
    {
        int row  = tid >> 2;
        int col0 = (tid & 3) << 4;
        int grow = qt * 64 + row;
        int bb = bh >> 4, h = bh & 15;
        float inv_l = 1.0f / l_s[row];
        size_t base = ((size_t)bb * S_ + grow) * H_ + h * HD_ + col0;
#pragma unroll
        for (int c = 0; c < 16; c++)
            g_att[base + c] = wmma::__float_to_tf32(Ss[row * LDS_T + col0 + c] * inv_l);
    }
}

// ---------------- launch -----------------------------------------------------
extern "C" void kernel_launch(void* const* d_in, const int* in_sizes, int n_in,
                              void* d_out, int out_size)
{
    const float* x     = (const float*)d_in[0];
    const float* w_qkv = (const float*)d_in[1];
    const float* b_qkv = (const float*)d_in[2];
    const float* w_out = (const float*)d_in[3];
    const float* b_out = (const float*)d_in[4];
    float* out = (float*)d_out;

    cudaFuncSetAttribute(gemm_tf32_kernel<0>,
                         cudaFuncAttributeMaxDynamicSharedMemorySize, GEMM_SMEM);
    cudaFuncSetAttribute(gemm_tf32_kernel<1>,
                         cudaFuncAttributeMaxDynamicSharedMemorySize, GEMM_SMEM);
    cudaFuncSetAttribute(attn_tf32_kernel,
                         cudaFuncAttributeMaxDynamicSharedMemorySize, ATTN_SMEM);

    round_tf32_kernel<0><<<(MR_ * H_ / 4 + 255) / 256, 256>>>((const float4*)x, MR_ * H_ / 4);
    round_tf32_kernel<1><<<(H_ * 3 * H_ / 4 + 255) / 256, 256>>>((const float4*)w_qkv, H_ * 3 * H_ / 4);
    round_tf32_kernel<2><<<(H_ * H_ / 4 + 255) / 256, 256>>>((const float4*)w_out, H_ * H_ / 4);

    dim3 g1((3 * H_) / BN, MR_ / BM);
    gemm_tf32_kernel<0><<<g1, 256, GEMM_SMEM>>>(b_qkv, nullptr, MR_, 3 * H_, H_);

    dim3 g2(S_ / 64, B_ * NH_);
    attn_tf32_kernel<<<g2, 256, ATTN_SMEM>>>();

    dim3 g3(H_ / BN, MR_ / BM);
    gemm_tf32_kernel<1><<<g3, 256, GEMM_SMEM>>>(b_out, out, MR_, H_, H_);
}

// round 8
// speedup vs baseline: 1.0599x; 1.0472x over previous
#include <cuda_runtime.h>
#include <cuda_bf16.h>
#include <mma.h>
#include <math.h>

using namespace nvcuda;

#define B_   2
#define S_   2048
#define H_   1024
#define NH_  16
#define HD_  64
#define MR_  (B_ * S_)
#define ATTN_SCALE 0.125f

// ---------------- scratch ----------------------------------------------------
__device__ float g_q[B_ * NH_ * S_ * HD_];   // (b,h,s,d)  tf32-rounded, q pre-scaled
__device__ float g_k[B_ * NH_ * S_ * HD_];
__device__ float g_v[B_ * NH_ * S_ * HD_];
__device__ float g_att[MR_ * H_];            // (b,s,H)    tf32-rounded
__device__ float g_x_t[MR_ * H_];            // tf32-rounded x
__device__ float g_wqkv_t[H_ * 3 * H_];      // tf32-rounded w_qkv
__device__ float g_wout_t[H_ * H_];          // tf32-rounded w_out

// ---------------- cp.async helpers ------------------------------------------
__device__ __forceinline__ unsigned smem_u32(const void* p) {
    return (unsigned)__cvta_generic_to_shared(p);
}
#define CP_ASYNC16(dst_u32, src_ptr) \
    asm volatile("cp.async.cg.shared.global [%0], [%1], 16;\n" :: "r"(dst_u32), "l"(src_ptr))
#define CP_COMMIT() asm volatile("cp.async.commit_group;\n" ::)
#define CP_WAIT(N)  asm volatile("cp.async.wait_group %0;\n" :: "n"(N))

// ---------------- prep: one fused tf32 rounding pass over x, w_qkv, w_out ----
#define N4_X  (MR_ * H_ / 4)
#define N4_WQ (H_ * 3 * H_ / 4)
#define N4_WO (H_ * H_ / 4)
#define N4_TOTAL (N4_X + N4_WQ + N4_WO)

__global__ void round_all_kernel(const float4* __restrict__ x,
                                 const float4* __restrict__ wqkv,
                                 const float4* __restrict__ wout)
{
    int i = blockIdx.x * blockDim.x + threadIdx.x;
    const float4* src;
    float4* dst;
    int j;
    if (i < N4_X)                { src = x;    dst = (float4*)g_x_t;    j = i; }
    else if (i < N4_X + N4_WQ)   { src = wqkv; dst = (float4*)g_wqkv_t; j = i - N4_X; }
    else if (i < N4_TOTAL)       { src = wout; dst = (float4*)g_wout_t; j = i - N4_X - N4_WQ; }
    else return;
    float4 v = src[j];
    v.x = wmma::__float_to_tf32(v.x);
    v.y = wmma::__float_to_tf32(v.y);
    v.z = wmma::__float_to_tf32(v.z);
    v.w = wmma::__float_to_tf32(v.w);
    dst[j] = v;
}

// ---------------- tf32 wmma GEMM (exact R4 structure: 2-stage, 2 syncs) ------
#define BM 128
#define BN 128
#define BK 32
#define LDA_S 40
#define LDB_S 136
#define A_STAGE (BM * LDA_S)
#define B_STAGE (BK * LDB_S)
#define GEMM_SMEM ((2 * A_STAGE + 2 * B_STAGE) * 4)   // ~74 KB -> 2 CTAs/SM

template <int EPI>
__global__ __launch_bounds__(256) void gemm_tf32_kernel(
    const float* __restrict__ bias, float* __restrict__ C,
    int M, int N, int K)
{
    const float* A  = (EPI == 1) ? (const float*)g_att    : (const float*)g_x_t;
    const float* Bw = (EPI == 1) ? (const float*)g_wout_t : (const float*)g_wqkv_t;

    extern __shared__ float sm[];
    float* As = sm;                    // [2][BM][LDA_S]
    float* Bs = sm + 2 * A_STAGE;      // [2][BK][LDB_S]

    const int bm   = blockIdx.y * BM;
    const int bn   = blockIdx.x * BN;
    const int tid  = threadIdx.x;
    const int warp = tid >> 5;
    const int lane = tid & 31;
    const int wm   = warp >> 2;
    const int wn   = warp & 3;

    wmma::fragment<wmma::accumulator, 16, 16, 8, float> acc[4][2];
#pragma unroll
    for (int i = 0; i < 4; i++)
#pragma unroll
        for (int j = 0; j < 2; j++) wmma::fill_fragment(acc[i][j], 0.0f);

    const int NIT = K / BK;

    auto load_stage = [&](int st, int k0) {
#pragma unroll
        for (int it = 0; it < 4; it++) {
            int f4 = tid + it * 256;
            int r  = f4 >> 3;
            int c4 = (f4 & 7) << 2;
            CP_ASYNC16(smem_u32(&As[st * A_STAGE + r * LDA_S + c4]),
                       &A[(size_t)(bm + r) * K + k0 + c4]);
        }
#pragma unroll
        for (int it = 0; it < 4; it++) {
            int f4 = tid + it * 256;
            int r  = f4 >> 5;
            int c4 = (f4 & 31) << 2;
            CP_ASYNC16(smem_u32(&Bs[st * B_STAGE + r * LDB_S + c4]),
                       &Bw[(size_t)(k0 + r) * N + bn + c4]);
        }
    };

    load_stage(0, 0);
    CP_COMMIT();

    for (int it = 0; it < NIT; it++) {
        if (it + 1 < NIT) {
            load_stage((it + 1) & 1, (it + 1) * BK);
            CP_COMMIT();
            CP_WAIT(1);
        } else {
            CP_WAIT(0);
        }
        __syncthreads();

        const float* Ac = &As[(it & 1) * A_STAGE];
        const float* Bc = &Bs[(it & 1) * B_STAGE];
#pragma unroll
        for (int kk = 0; kk < BK / 8; kk++) {
            wmma::fragment<wmma::matrix_a, 16, 16, 8, wmma::precision::tf32, wmma::row_major> af[4];
            wmma::fragment<wmma::matrix_b, 16, 16, 8, wmma::precision::tf32, wmma::row_major> bf[2];
#pragma unroll
            for (int i = 0; i < 4; i++)
                wmma::load_matrix_sync(af[i], &Ac[(wm * 64 + i * 16) * LDA_S + kk * 8], LDA_S);
#pragma unroll
            for (int j = 0; j < 2; j++)
                wmma::load_matrix_sync(bf[j], &Bc[(kk * 8) * LDB_S + wn * 32 + j * 16], LDB_S);
#pragma unroll
            for (int i = 0; i < 4; i++)
#pragma unroll
                for (int j = 0; j < 2; j++)
                    wmma::mma_sync(acc[i][j], af[i], bf[j], acc[i][j]);
        }
        __syncthreads();
    }

    float* scr = &As[warp * 16 * 20];
#pragma unroll
    for (int i = 0; i < 4; i++) {
#pragma unroll
        for (int j = 0; j < 2; j++) {
            wmma::store_matrix_sync(scr, acc[i][j], 20, wmma::mem_row_major);
            __syncwarp();
#pragma unroll
            for (int e = 0; e < 8; e++) {
                int idx = lane + e * 32;
                int rr = idx >> 4, cc = idx & 15;
                int m = bm + wm * 64 + i * 16 + rr;
                int n = bn + wn * 32 + j * 16 + cc;
                float val = scr[rr * 20 + cc] + bias[n];
                if (EPI == 0) {
                    int which = n >> 10;           // 0=q 1=k 2=v
                    int hn = n & (H_ - 1);
                    int h  = hn >> 6;
                    int d  = hn & (HD_ - 1);
                    int bb = m >> 11;
                    int s  = m & (S_ - 1);
                    if (which == 0) val *= ATTN_SCALE;
                    val = wmma::__float_to_tf32(val);
                    size_t dst = ((size_t)(bb * NH_ + h) * S_ + s) * HD_ + d;
                    float* T = (which == 0) ? g_q : (which == 1) ? g_k : g_v;
                    T[dst] = val;
                } else {
                    C[(size_t)m * N + n] = val;
                }
            }
            __syncwarp();
        }
    }
}

// ---------------- tf32 wmma attention (mask: allow j >= i) -------------------
// 64x64 tiles, 8 warps: wr=warp>>1 rows, wc=warp&1 cols.
// Non-diagonal tiles (i>0): exp applied elementwise IN-REGISTER on the score
// fragment (no layout knowledge needed), so the smem S->P rewrite pass and one
// barrier disappear: 2 syncs/tile. Diagonal tile (i==0) keeps the masked smem
// path (3 syncs). Row sums read P from smem read-only, concurrent with PV.
#define LDS_T 72
#define KV_STAGE (64 * LDS_T)
#define ATTN_SMEM ((4 * KV_STAGE + KV_STAGE + 64) * 4)

__global__ __launch_bounds__(256) void attn_tf32_kernel()
{
    extern __shared__ float sm[];
    float* Ks  = sm;                   // [2][64][LDS_T]
    float* Vs  = sm + 2 * KV_STAGE;    // [2][64][LDS_T]
    float* Ss  = sm + 4 * KV_STAGE;    // [64][LDS_T]
    float* l_s = sm + 5 * KV_STAGE;    // [64]

    const int qt = blockIdx.x;
    const int bh = blockIdx.y;
    const float* Qb = g_q + (size_t)bh * S_ * HD_;
    const float* Kb = g_k + (size_t)bh * S_ * HD_;
    const float* Vb = g_v + (size_t)bh * S_ * HD_;

    const int tid  = threadIdx.x;
    const int warp = tid >> 5;
    const int wr   = warp >> 1;
    const int wc   = warp & 1;

    auto load_kv = [&](int st, int kt) {
#pragma unroll
        for (int it = 0; it < 4; it++) {
            int f4 = tid + it * 256;
            int r  = f4 >> 4;
            int c4 = (f4 & 15) << 2;
            size_t src = (size_t)(kt * 64 + r) * HD_ + c4;
            CP_ASYNC16(smem_u32(&Ks[st * KV_STAGE + r * LDS_T + c4]), &Kb[src]);
            CP_ASYNC16(smem_u32(&Vs[st * KV_STAGE + r * LDS_T + c4]), &Vb[src]);
        }
    };

    const int nkt = S_ / 64 - qt;
    load_kv(0, qt);
    CP_COMMIT();

    // stage Q into Ss (already scaled + rounded)
    for (int idx = tid; idx < 64 * HD_; idx += 256) {
        int r = idx >> 6, c = idx & 63;
        Ss[r * LDS_T + c] = Qb[(size_t)(qt * 64 + r) * HD_ + c];
    }
    if (tid < 64) l_s[tid] = 0.0f;
    __syncthreads();

    wmma::fragment<wmma::matrix_a, 16, 16, 8, wmma::precision::tf32, wmma::row_major> qf[8];
#pragma unroll
    for (int kk = 0; kk < 8; kk++)
        wmma::load_matrix_sync(qf[kk], &Ss[(wr * 16) * LDS_T + kk * 8], LDS_T);

    wmma::fragment<wmma::accumulator, 16, 16, 8, float> o_acc[2];
    wmma::fill_fragment(o_acc[0], 0.0f);
    wmma::fill_fragment(o_acc[1], 0.0f);
    // first in-loop sync [A] orders qf loads (all warps) before Ss reuse

    for (int i = 0; i < nkt; i++) {
        const int kt = qt + i;
        CP_WAIT(0);
        __syncthreads();                    // [A] KV stage i visible; other slot free
        if (i + 1 < nkt) {
            load_kv((i + 1) & 1, kt + 1);   // overlaps this tile's compute
            CP_COMMIT();
        }
        const float* Kc = &Ks[(i & 1) * KV_STAGE];
        const float* Vc = &Vs[(i & 1) * KV_STAGE];

        // S = Q @ K^T
        wmma::fragment<wmma::accumulator, 16, 16, 8, float> s_acc[2];
        wmma::fill_fragment(s_acc[0], 0.0f);
        wmma::fill_fragment(s_acc[1], 0.0f);
#pragma unroll
        for (int kk = 0; kk < 8; kk++) {
            wmma::fragment<wmma::matrix_b, 16, 16, 8, wmma::precision::tf32, wmma::col_major> kf[2];
#pragma unroll
            for (int j = 0; j < 2; j++)
                wmma::load_matrix_sync(kf[j], &Kc[(wc * 32 + j * 16) * LDS_T + kk * 8], LDS_T);
            wmma::mma_sync(s_acc[0], qf[kk], kf[0], s_acc[0]);
            wmma::mma_sync(s_acc[1], qf[kk], kf[1], s_acc[1]);
        }

        if (i == 0) {
            // ---- diagonal tile: masked path via smem (3 syncs) ----
            wmma::store_matrix_sync(&Ss[(wr * 16) * LDS_T + wc * 32],      s_acc[0], LDS_T, wmma::mem_row_major);
            wmma::store_matrix_sync(&Ss[(wr * 16) * LDS_T + wc * 32 + 16], s_acc[1], LDS_T, wmma::mem_row_major);
            __syncthreads();                // [B] raw S visible

            int row  = tid >> 2;
            int col0 = (tid & 3) << 4;
            int grow = qt * 64 + row;
            float part = 0.0f;
#pragma unroll
            for (int c = 0; c < 16; c++) {
                int gcol = kt * 64 + col0 + c;
                float s = Ss[row * LDS_T + col0 + c];
                float p = (gcol >= grow) ? __expf(s) : 0.0f;
                p = wmma::__float_to_tf32(p);
                Ss[row * LDS_T + col0 + c] = p;
                part += p;
            }
            part += __shfl_xor_sync(0xffffffffu, part, 1);
            part += __shfl_xor_sync(0xffffffffu, part, 2);
            if ((tid & 3) == 0) l_s[row] += part;
            __syncthreads();                // [C] P visible to PV mma
        } else {
            // ---- fast path: exp + round in-register (elementwise, layout-free)
#pragma unroll
            for (int t = 0; t < s_acc[0].num_elements; t++)
                s_acc[0].x[t] = wmma::__float_to_tf32(__expf(s_acc[0].x[t]));
#pragma unroll
            for (int t = 0; t < s_acc[1].num_elements; t++)
                s_acc[1].x[t] = wmma::__float_to_tf32(__expf(s_acc[1].x[t]));
            wmma::store_matrix_sync(&Ss[(wr * 16) * LDS_T + wc * 32],      s_acc[0], LDS_T, wmma::mem_row_major);
            wmma::store_matrix_sync(&Ss[(wr * 16) * LDS_T + wc * 32 + 16], s_acc[1], LDS_T, wmma::mem_row_major);
            __syncthreads();                // [B] P visible (read-only below)

            // row sums (reads P; concurrent with PV fragment loads — both read-only)
            int row  = tid >> 2;
            int col0 = (tid & 3) << 4;
            float part = 0.0f;
#pragma unroll
            for (int c = 0; c < 16; c++)
                part += Ss[row * LDS_T + col0 + c];
            part += __shfl_xor_sync(0xffffffffu, part, 1);
            part += __shfl_xor_sync(0xffffffffu, part, 2);
            if ((tid & 3) == 0) l_s[row] += part;
            // no sync: next write to Ss is after next iteration's [A]
        }

        // O += P @ V
#pragma unroll
        for (int kk = 0; kk < 8; kk++) {
            wmma::fragment<wmma::matrix_a, 16, 16, 8, wmma::precision::tf32, wmma::row_major> pf;
            wmma::load_matrix_sync(pf, &Ss[(wr * 16) * LDS_T + kk * 8], LDS_T);
            wmma::fragment<wmma::matrix_b, 16, 16, 8, wmma::precision::tf32, wmma::row_major> vf[2];
#pragma unroll
            for (int j = 0; j < 2; j++)
                wmma::load_matrix_sync(vf[j], &Vc[(kk * 8) * LDS_T + wc * 32 + j * 16], LDS_T);
            wmma::mma_sync(o_acc[0], pf, vf[0], o_acc[0]);
            wmma::mma_sync(o_acc[1], pf, vf[1], o_acc[1]);
        }
    }
    __syncthreads();   // all PV reads of Ss done before o_acc stores reuse it

    // O / l -> g_att (b, s, H), tf32-rounded
    wmma::store_matrix_sync(&Ss[(wr * 16) * LDS_T + wc * 32],      o_acc[0], LDS_T, wmma::mem_row_major);
    wmma::store_matrix_sync(&Ss[(wr * 16) * LDS_T + wc * 32 + 16], o_acc[1], LDS_T, wmma::mem_row_major);
    __syncthreads();
    {
        int row  = tid >> 2;
        int col0 = (tid & 3) << 4;
        int grow = qt * 64 + row;
        int bb = bh >> 4, h = bh & 15;
        float inv_l = 1.0f / l_s[row];
        size_t base = ((size_t)bb * S_ + grow) * H_ + h * HD_ + col0;
#pragma unroll
        for (int c = 0; c < 16; c++)
            g_att[base + c] = wmma::__float_to_tf32(Ss[row * LDS_T + col0 + c] * inv_l);
    }
}

// ---------------- launch -----------------------------------------------------
extern "C" void kernel_launch(void* const* d_in, const int* in_sizes, int n_in,
                              void* d_out, int out_size)
{
    const float* x     = (const float*)d_in[0];
    const float* w_qkv = (const float*)d_in[1];
    const float* b_qkv = (const float*)d_in[2];
    const float* w_out = (const float*)d_in[3];
    const float* b_out = (const float*)d_in[4];
    float* out = (float*)d_out;

    cudaFuncSetAttribute(gemm_tf32_kernel<0>,
                         cudaFuncAttributeMaxDynamicSharedMemorySize, GEMM_SMEM);
    cudaFuncSetAttribute(gemm_tf32_kernel<1>,
                         cudaFuncAttributeMaxDynamicSharedMemorySize, GEMM_SMEM);
    cudaFuncSetAttribute(attn_tf32_kernel,
                         cudaFuncAttributeMaxDynamicSharedMemorySize, ATTN_SMEM);

    round_all_kernel<<<(N4_TOTAL + 255) / 256, 256>>>(
        (const float4*)x, (const float4*)w_qkv, (const float4*)w_out);

    dim3 g1((3 * H_) / BN, MR_ / BM);
    gemm_tf32_kernel<0><<<g1, 256, GEMM_SMEM>>>(b_qkv, nullptr, MR_, 3 * H_, H_);

    dim3 g2(S_ / 64, B_ * NH_);
    attn_tf32_kernel<<<g2, 256, ATTN_SMEM>>>();

    dim3 g3(H_ / BN, MR_ / BM);
    gemm_tf32_kernel<1><<<g3, 256, GEMM_SMEM>>>(b_out, out, MR_, H_, H_);
}

// round 9
// speedup vs baseline: 1.1266x; 1.0629x over previous
#include <cuda_runtime.h>
#include <cuda_bf16.h>
#include <mma.h>
#include <math.h>

using namespace nvcuda;

#define B_   2
#define S_   2048
#define H_   1024
#define NH_  16
#define HD_  64
#define MR_  (B_ * S_)
#define ATTN_SCALE 0.125f

// ---------------- scratch ----------------------------------------------------
__device__ float g_q[B_ * NH_ * S_ * HD_];   // (b,h,s,d)  tf32-rounded, q pre-scaled
__device__ float g_k[B_ * NH_ * S_ * HD_];
__device__ float g_v[B_ * NH_ * S_ * HD_];
__device__ float g_att[MR_ * H_];            // (b,s,H)    tf32-rounded
__device__ float g_x_t[MR_ * H_];            // tf32-rounded x
__device__ float g_wqkv_t[H_ * 3 * H_];      // tf32-rounded w_qkv
__device__ float g_wout_t[H_ * H_];          // tf32-rounded w_out

// ---------------- cp.async helpers ------------------------------------------
__device__ __forceinline__ unsigned smem_u32(const void* p) {
    return (unsigned)__cvta_generic_to_shared(p);
}
#define CP_ASYNC16(dst_u32, src_ptr) \
    asm volatile("cp.async.cg.shared.global [%0], [%1], 16;\n" :: "r"(dst_u32), "l"(src_ptr))
#define CP_COMMIT() asm volatile("cp.async.commit_group;\n" ::)
#define CP_WAIT(N)  asm volatile("cp.async.wait_group %0;\n" :: "n"(N))

// ---------------- prep: one fused tf32 rounding pass over x, w_qkv, w_out ----
#define N4_X  (MR_ * H_ / 4)
#define N4_WQ (H_ * 3 * H_ / 4)
#define N4_WO (H_ * H_ / 4)
#define N4_TOTAL (N4_X + N4_WQ + N4_WO)

__global__ void round_all_kernel(const float4* __restrict__ x,
                                 const float4* __restrict__ wqkv,
                                 const float4* __restrict__ wout)
{
    int i = blockIdx.x * blockDim.x + threadIdx.x;
    const float4* src;
    float4* dst;
    int j;
    if (i < N4_X)                { src = x;    dst = (float4*)g_x_t;    j = i; }
    else if (i < N4_X + N4_WQ)   { src = wqkv; dst = (float4*)g_wqkv_t; j = i - N4_X; }
    else if (i < N4_TOTAL)       { src = wout; dst = (float4*)g_wout_t; j = i - N4_X - N4_WQ; }
    else return;
    float4 v = src[j];
    v.x = wmma::__float_to_tf32(v.x);
    v.y = wmma::__float_to_tf32(v.y);
    v.z = wmma::__float_to_tf32(v.z);
    v.w = wmma::__float_to_tf32(v.w);
    dst[j] = v;
}

// ---------------- tf32 wmma GEMM: 4 warps, 64x64 warp tiles ------------------
// BM=BN=128, BK=32, 128 threads = 4 warps (2x2). Each warp: 4x4 accum frags.
// Fragment reuse 16 MMAs / 8 loads per kk-step (2x the old 64x32 tiling);
// barrier population halved. 2-stage cp.async, ~76KB smem -> 2 CTAs/SM.
#define BM 128
#define BN 128
#define BK 32
#define LDA_S 40
#define LDB_S 136
#define A_STAGE (BM * LDA_S)
#define B_STAGE (BK * LDB_S)
#define GEMM_SMEM ((2 * A_STAGE + 2 * B_STAGE) * 4)

template <int EPI>
__global__ __launch_bounds__(128) void gemm_tf32_kernel(
    const float* __restrict__ bias, float* __restrict__ C,
    int M, int N, int K)
{
    const float* A  = (EPI == 1) ? (const float*)g_att    : (const float*)g_x_t;
    const float* Bw = (EPI == 1) ? (const float*)g_wout_t : (const float*)g_wqkv_t;

    extern __shared__ float sm[];
    float* As = sm;                    // [2][BM][LDA_S]
    float* Bs = sm + 2 * A_STAGE;      // [2][BK][LDB_S]

    const int bm   = blockIdx.y * BM;
    const int bn   = blockIdx.x * BN;
    const int tid  = threadIdx.x;
    const int warp = tid >> 5;
    const int lane = tid & 31;
    const int wm   = warp >> 1;        // 0..1
    const int wn   = warp & 1;         // 0..1

    wmma::fragment<wmma::accumulator, 16, 16, 8, float> acc[4][4];
#pragma unroll
    for (int i = 0; i < 4; i++)
#pragma unroll
        for (int j = 0; j < 4; j++) wmma::fill_fragment(acc[i][j], 0.0f);

    const int NIT = K / BK;

    auto load_stage = [&](int st, int k0) {
#pragma unroll
        for (int it = 0; it < 8; it++) {
            int f4 = tid + it * 128;               // 0..1023
            int r  = f4 >> 3;
            int c4 = (f4 & 7) << 2;
            CP_ASYNC16(smem_u32(&As[st * A_STAGE + r * LDA_S + c4]),
                       &A[(size_t)(bm + r) * K + k0 + c4]);
        }
#pragma unroll
        for (int it = 0; it < 8; it++) {
            int f4 = tid + it * 128;
            int r  = f4 >> 5;
            int c4 = (f4 & 31) << 2;
            CP_ASYNC16(smem_u32(&Bs[st * B_STAGE + r * LDB_S + c4]),
                       &Bw[(size_t)(k0 + r) * N + bn + c4]);
        }
    };

    load_stage(0, 0);
    CP_COMMIT();

    for (int it = 0; it < NIT; it++) {
        if (it + 1 < NIT) {
            load_stage((it + 1) & 1, (it + 1) * BK);
            CP_COMMIT();
            CP_WAIT(1);
        } else {
            CP_WAIT(0);
        }
        __syncthreads();

        const float* Ac = &As[(it & 1) * A_STAGE];
        const float* Bc = &Bs[(it & 1) * B_STAGE];
#pragma unroll
        for (int kk = 0; kk < BK / 8; kk++) {
            wmma::fragment<wmma::matrix_a, 16, 16, 8, wmma::precision::tf32, wmma::row_major> af[4];
            wmma::fragment<wmma::matrix_b, 16, 16, 8, wmma::precision::tf32, wmma::row_major> bf[4];
#pragma unroll
            for (int i = 0; i < 4; i++)
                wmma::load_matrix_sync(af[i], &Ac[(wm * 64 + i * 16) * LDA_S + kk * 8], LDA_S);
#pragma unroll
            for (int j = 0; j < 4; j++)
                wmma::load_matrix_sync(bf[j], &Bc[(kk * 8) * LDB_S + wn * 64 + j * 16], LDB_S);
#pragma unroll
            for (int i = 0; i < 4; i++)
#pragma unroll
                for (int j = 0; j < 4; j++)
                    wmma::mma_sync(acc[i][j], af[i], bf[j], acc[i][j]);
        }
        __syncthreads();
    }

    // epilogue via per-warp smem scratch (reuses As)
    float* scr = &As[warp * 16 * 20];
#pragma unroll
    for (int i = 0; i < 4; i++) {
#pragma unroll
        for (int j = 0; j < 4; j++) {
            wmma::store_matrix_sync(scr, acc[i][j], 20, wmma::mem_row_major);
            __syncwarp();
#pragma unroll
            for (int e = 0; e < 8; e++) {
                int idx = lane + e * 32;
                int rr = idx >> 4, cc = idx & 15;
                int m = bm + wm * 64 + i * 16 + rr;
                int n = bn + wn * 64 + j * 16 + cc;
                float val = scr[rr * 20 + cc] + bias[n];
                if (EPI == 0) {
                    int which = n >> 10;           // 0=q 1=k 2=v
                    int hn = n & (H_ - 1);
                    int h  = hn >> 6;
                    int d  = hn & (HD_ - 1);
                    int bb = m >> 11;
                    int s  = m & (S_ - 1);
                    if (which == 0) val *= ATTN_SCALE;
                    val = wmma::__float_to_tf32(val);
                    size_t dst = ((size_t)(bb * NH_ + h) * S_ + s) * HD_ + d;
                    float* T = (which == 0) ? g_q : (which == 1) ? g_k : g_v;
                    T[dst] = val;
                } else {
                    C[(size_t)m * N + n] = val;
                }
            }
            __syncwarp();
        }
    }
}

// ---------------- tf32 wmma attention (mask: allow j >= i) -------------------
// (unchanged from R8)
#define LDS_T 72
#define KV_STAGE (64 * LDS_T)
#define ATTN_SMEM ((4 * KV_STAGE + KV_STAGE + 64) * 4)

__global__ __launch_bounds__(256) void attn_tf32_kernel()
{
    extern __shared__ float sm[];
    float* Ks  = sm;                   // [2][64][LDS_T]
    float* Vs  = sm + 2 * KV_STAGE;    // [2][64][LDS_T]
    float* Ss  = sm + 4 * KV_STAGE;    // [64][LDS_T]
    float* l_s = sm + 5 * KV_STAGE;    // [64]

    const int qt = blockIdx.x;
    const int bh = blockIdx.y;
    const float* Qb = g_q + (size_t)bh * S_ * HD_;
    const float* Kb = g_k + (size_t)bh * S_ * HD_;
    const float* Vb = g_v + (size_t)bh * S_ * HD_;

    const int tid  = threadIdx.x;
    const int warp = tid >> 5;
    const int wr   = warp >> 1;
    const int wc   = warp & 1;

    auto load_kv = [&](int st, int kt) {
#pragma unroll
        for (int it = 0; it < 4; it++) {
            int f4 = tid + it * 256;
            int r  = f4 >> 4;
            int c4 = (f4 & 15) << 2;
            size_t src = (size_t)(kt * 64 + r) * HD_ + c4;
            CP_ASYNC16(smem_u32(&Ks[st * KV_STAGE + r * LDS_T + c4]), &Kb[src]);
            CP_ASYNC16(smem_u32(&Vs[st * KV_STAGE + r * LDS_T + c4]), &Vb[src]);
        }
    };

    const int nkt = S_ / 64 - qt;
    load_kv(0, qt);
    CP_COMMIT();

    for (int idx = tid; idx < 64 * HD_; idx += 256) {
        int r = idx >> 6, c = idx & 63;
        Ss[r * LDS_T + c] = Qb[(size_t)(qt * 64 + r) * HD_ + c];
    }
    if (tid < 64) l_s[tid] = 0.0f;
    __syncthreads();

    wmma::fragment<wmma::matrix_a, 16, 16, 8, wmma::precision::tf32, wmma::row_major> qf[8];
#pragma unroll
    for (int kk = 0; kk < 8; kk++)
        wmma::load_matrix_sync(qf[kk], &Ss[(wr * 16) * LDS_T + kk * 8], LDS_T);

    wmma::fragment<wmma::accumulator, 16, 16, 8, float> o_acc[2];
    wmma::fill_fragment(o_acc[0], 0.0f);
    wmma::fill_fragment(o_acc[1], 0.0f);

    for (int i = 0; i < nkt; i++) {
        const int kt = qt + i;
        CP_WAIT(0);
        __syncthreads();                    // [A] KV stage i visible; other slot free
        if (i + 1 < nkt) {
            load_kv((i + 1) & 1, kt + 1);
            CP_COMMIT();
        }
        const float* Kc = &Ks[(i & 1) * KV_STAGE];
        const float* Vc = &Vs[(i & 1) * KV_STAGE];

        wmma::fragment<wmma::accumulator, 16, 16, 8, float> s_acc[2];
        wmma::fill_fragment(s_acc[0], 0.0f);
        wmma::fill_fragment(s_acc[1], 0.0f);
#pragma unroll
        for (int kk = 0; kk < 8; kk++) {
            wmma::fragment<wmma::matrix_b, 16, 16, 8, wmma::precision::tf32, wmma::col_major> kf[2];
#pragma unroll
            for (int j = 0; j < 2; j++)
                wmma::load_matrix_sync(kf[j], &Kc[(wc * 32 + j * 16) * LDS_T + kk * 8], LDS_T);
            wmma::mma_sync(s_acc[0], qf[kk], kf[0], s_acc[0]);
            wmma::mma_sync(s_acc[1], qf[kk], kf[1], s_acc[1]);
        }

        if (i == 0) {
            wmma::store_matrix_sync(&Ss[(wr * 16) * LDS_T + wc * 32],      s_acc[0], LDS_T, wmma::mem_row_major);
            wmma::store_matrix_sync(&Ss[(wr * 16) * LDS_T + wc * 32 + 16], s_acc[1], LDS_T, wmma::mem_row_major);
            __syncthreads();

            int row  = tid >> 2;
            int col0 = (tid & 3) << 4;
            int grow = qt * 64 + row;
            float part = 0.0f;
#pragma unroll
            for (int c = 0; c < 16; c++) {
                int gcol = kt * 64 + col0 + c;
                float s = Ss[row * LDS_T + col0 + c];
                float p = (gcol >= grow) ? __expf(s) : 0.0f;
                p = wmma::__float_to_tf32(p);
                Ss[row * LDS_T + col0 + c] = p;
                part += p;
            }
            part += __shfl_xor_sync(0xffffffffu, part, 1);
            part += __shfl_xor_sync(0xffffffffu, part, 2);
            if ((tid & 3) == 0) l_s[row] += part;
            __syncthreads();
        } else {
#pragma unroll
            for (int t = 0; t < s_acc[0].num_elements; t++)
                s_acc[0].x[t] = wmma::__float_to_tf32(__expf(s_acc[0].x[t]));
#pragma unroll
            for (int t = 0; t < s_acc[1].num_elements; t++)
                s_acc[1].x[t] = wmma::__float_to_tf32(__expf(s_acc[1].x[t]));
            wmma::store_matrix_sync(&Ss[(wr * 16) * LDS_T + wc * 32],      s_acc[0], LDS_T, wmma::mem_row_major);
            wmma::store_matrix_sync(&Ss[(wr * 16) * LDS_T + wc * 32 + 16], s_acc[1], LDS_T, wmma::mem_row_major);
            __syncthreads();

            int row  = tid >> 2;
            int col0 = (tid & 3) << 4;
            float part = 0.0f;
#pragma unroll
            for (int c = 0; c < 16; c++)
                part += Ss[row * LDS_T + col0 + c];
            part += __shfl_xor_sync(0xffffffffu, part, 1);
            part += __shfl_xor_sync(0xffffffffu, part, 2);
            if ((tid & 3) == 0) l_s[row] += part;
        }

        // O += P @ V
#pragma unroll
        for (int kk = 0; kk < 8; kk++) {
            wmma::fragment<wmma::matrix_a, 16, 16, 8, wmma::precision::tf32, wmma::row_major> pf;
            wmma::load_matrix_sync(pf, &Ss[(wr * 16) * LDS_T + kk * 8], LDS_T);
            wmma::fragment<wmma::matrix_b, 16, 16, 8, wmma::precision::tf32, wmma::row_major> vf[2];
#pragma unroll
            for (int j = 0; j < 2; j++)
                wmma::load_matrix_sync(vf[j], &Vc[(kk * 8) * LDS_T + wc * 32 + j * 16], LDS_T);
            wmma::mma_sync(o_acc[0], pf, vf[0], o_acc[0]);
            wmma::mma_sync(o_acc[1], pf, vf[1], o_acc[1]);
        }
    }
    __syncthreads();

    wmma::store_matrix_sync(&Ss[(wr * 16) * LDS_T + wc * 32],      o_acc[0], LDS_T, wmma::mem_row_major);
    wmma::store_matrix_sync(&Ss[(wr * 16) * LDS_T + wc * 32 + 16], o_acc[1], LDS_T, wmma::mem_row_major);
    __syncthreads();
    {
        int row  = tid >> 2;
        int col0 = (tid & 3) << 4;
        int grow = qt * 64 + row;
        int bb = bh >> 4, h = bh & 15;
        float inv_l = 1.0f / l_s[row];
        size_t base = ((size_t)bb * S_ + grow) * H_ + h * HD_ + col0;
#pragma unroll
        for (int c = 0; c < 16; c++)
            g_att[base + c] = wmma::__float_to_tf32(Ss[row * LDS_T + col0 + c] * inv_l);
    }
}

// ---------------- launch -----------------------------------------------------
extern "C" void kernel_launch(void* const* d_in, const int* in_sizes, int n_in,
                              void* d_out, int out_size)
{
    const float* x     = (const float*)d_in[0];
    const float* w_qkv = (const float*)d_in[1];
    const float* b_qkv = (const float*)d_in[2];
    const float* w_out = (const float*)d_in[3];
    const float* b_out = (const float*)d_in[4];
    float* out = (float*)d_out;

    cudaFuncSetAttribute(gemm_tf32_kernel<0>,
                         cudaFuncAttributeMaxDynamicSharedMemorySize, GEMM_SMEM);
    cudaFuncSetAttribute(gemm_tf32_kernel<1>,
                         cudaFuncAttributeMaxDynamicSharedMemorySize, GEMM_SMEM);
    cudaFuncSetAttribute(attn_tf32_kernel,
                         cudaFuncAttributeMaxDynamicSharedMemorySize, ATTN_SMEM);

    round_all_kernel<<<(N4_TOTAL + 255) / 256, 256>>>(
        (const float4*)x, (const float4*)w_qkv, (const float4*)w_out);

    dim3 g1((3 * H_) / BN, MR_ / BM);
    gemm_tf32_kernel<0><<<g1, 128, GEMM_SMEM>>>(b_qkv, nullptr, MR_, 3 * H_, H_);

    dim3 g2(S_ / 64, B_ * NH_);
    attn_tf32_kernel<<<g2, 256, ATTN_SMEM>>>();

    dim3 g3(H_ / BN, MR_ / BM);
    gemm_tf32_kernel<1><<<g3, 128, GEMM_SMEM>>>(b_out, out, MR_, H_, H_);
}

// round 11
// speedup vs baseline: 2.2879x; 2.0308x over previous
#include <cuda_runtime.h>
#include <cuda_fp16.h>
#include <mma.h>
#include <math.h>
#include <cstdint>

using namespace nvcuda;

#define B_   2
#define S_   2048
#define H_   1024
#define NH_  16
#define HD_  64
#define MR_  (B_ * S_)
#define ATTN_SCALE 0.125f

// ---------------- scratch (half everywhere on the MMA paths) -----------------
__device__ __half g_x_h[MR_ * H_];           // fp16 x            [M][K]
__device__ __half g_wqkv_h[H_ * 3 * H_];     // fp16 w_qkv        [K][N]
__device__ __half g_wout_h[H_ * H_];         // fp16 w_out        [K][N]
__device__ __half g_q[B_ * NH_ * S_ * HD_];  // (b,h,s,d) q pre-scaled
__device__ __half g_k[B_ * NH_ * S_ * HD_];
__device__ __half g_v[B_ * NH_ * S_ * HD_];
__device__ __half g_att[MR_ * H_];           // (b,s,H)

// ---------------- cp.async helpers ------------------------------------------
__device__ __forceinline__ unsigned smem_u32(const void* p) {
    return (unsigned)__cvta_generic_to_shared(p);
}
#define CP_ASYNC16(dst_u32, src_ptr) \
    asm volatile("cp.async.cg.shared.global [%0], [%1], 16;\n" :: "r"(dst_u32), "l"(src_ptr))
#define CP_COMMIT() asm volatile("cp.async.commit_group;\n" ::)
#define CP_WAIT(N)  asm volatile("cp.async.wait_group %0;\n" :: "n"(N))

// ---------------- prep: fused fp32 -> fp16 conversion ------------------------
#define N4_X  (MR_ * H_ / 4)
#define N4_WQ (H_ * 3 * H_ / 4)
#define N4_WO (H_ * H_ / 4)
#define N4_TOTAL (N4_X + N4_WQ + N4_WO)

__global__ void tohalf_all_kernel(const float4* __restrict__ x,
                                  const float4* __restrict__ wqkv,
                                  const float4* __restrict__ wout)
{
    int i = blockIdx.x * blockDim.x + threadIdx.x;
    const float4* src;
    __half2* dst;
    int j;
    if (i < N4_X)              { src = x;    dst = (__half2*)g_x_h;    j = i; }
    else if (i < N4_X + N4_WQ) { src = wqkv; dst = (__half2*)g_wqkv_h; j = i - N4_X; }
    else if (i < N4_TOTAL)     { src = wout; dst = (__half2*)g_wout_h; j = i - N4_X - N4_WQ; }
    else return;
    float4 v = src[j];
    dst[2 * j]     = __floats2half2_rn(v.x, v.y);
    dst[2 * j + 1] = __floats2half2_rn(v.z, v.w);
}

// ---------------- fp16 wmma GEMM: 4 warps, 64x64 warp tiles ------------------
// BM=BN=128, BK=32 (2 k16-steps), 128 threads (2x2 warps), 2-stage cp.async.
#define BM 128
#define BN 128
#define BK 32
#define LDA_H 48     // 32 + 16 pad halves (96B rows, 32B-aligned)
#define LDB_H 144    // 128 + 16 pad halves (288B rows)
#define A_STAGE_H (BM * LDA_H)     // 6144 halves
#define B_STAGE_H (BK * LDB_H)     // 4608 halves
#define GEMM_SMEM ((2 * A_STAGE_H + 2 * B_STAGE_H) * 2)   // 43008 B

template <int EPI>
__global__ __launch_bounds__(128) void gemm_fp16_kernel(
    const float* __restrict__ bias, float* __restrict__ C,
    int M, int N, int K)
{
    const __half* A  = (EPI == 1) ? (const __half*)g_att    : (const __half*)g_x_h;
    const __half* Bw = (EPI == 1) ? (const __half*)g_wout_h : (const __half*)g_wqkv_h;

    extern __shared__ __half smh[];
    __half* As = smh;                      // [2][BM][LDA_H]
    __half* Bs = smh + 2 * A_STAGE_H;      // [2][BK][LDB_H]

    const int bm   = blockIdx.y * BM;
    const int bn   = blockIdx.x * BN;
    const int tid  = threadIdx.x;
    const int warp = tid >> 5;
    const int lane = tid & 31;
    const int wm   = warp >> 1;        // 0..1
    const int wn   = warp & 1;         // 0..1

    wmma::fragment<wmma::accumulator, 16, 16, 16, float> acc[4][4];
#pragma unroll
    for (int i = 0; i < 4; i++)
#pragma unroll
        for (int j = 0; j < 4; j++) wmma::fill_fragment(acc[i][j], 0.0f);

    const int NIT = K / BK;

    auto load_stage = [&](int st, int k0) {
        // A: 128 rows x 32 halves = 512 x 16B chunks
#pragma unroll
        for (int it = 0; it < 4; it++) {
            int idx = tid + it * 128;
            int r   = idx >> 2;
            int c8  = (idx & 3) << 3;
            CP_ASYNC16(smem_u32(&As[st * A_STAGE_H + r * LDA_H + c8]),
                       &A[(size_t)(bm + r) * K + k0 + c8]);
        }
        // B: 32 rows x 128 halves = 512 x 16B chunks
#pragma unroll
        for (int it = 0; it < 4; it++) {
            int idx = tid + it * 128;
            int r   = idx >> 4;
            int c8  = (idx & 15) << 3;
            CP_ASYNC16(smem_u32(&Bs[st * B_STAGE_H + r * LDB_H + c8]),
                       &Bw[(size_t)(k0 + r) * N + bn + c8]);
        }
    };

    load_stage(0, 0);
    CP_COMMIT();

    for (int it = 0; it < NIT; it++) {
        if (it + 1 < NIT) {
            load_stage((it + 1) & 1, (it + 1) * BK);
            CP_COMMIT();
            CP_WAIT(1);
        } else {
            CP_WAIT(0);
        }
        __syncthreads();

        const __half* Ac = &As[(it & 1) * A_STAGE_H];
        const __half* Bc = &Bs[(it & 1) * B_STAGE_H];
#pragma unroll
        for (int kk = 0; kk < BK / 16; kk++) {
            wmma::fragment<wmma::matrix_a, 16, 16, 16, __half, wmma::row_major> af[4];
            wmma::fragment<wmma::matrix_b, 16, 16, 16, __half, wmma::row_major> bf[4];
#pragma unroll
            for (int i = 0; i < 4; i++)
                wmma::load_matrix_sync(af[i], &Ac[(wm * 64 + i * 16) * LDA_H + kk * 16], LDA_H);
#pragma unroll
            for (int j = 0; j < 4; j++)
                wmma::load_matrix_sync(bf[j], &Bc[(kk * 16) * LDB_H + wn * 64 + j * 16], LDB_H);
#pragma unroll
            for (int i = 0; i < 4; i++)
#pragma unroll
                for (int j = 0; j < 4; j++)
                    wmma::mma_sync(acc[i][j], af[i], bf[j], acc[i][j]);
        }
        __syncthreads();
    }

    // epilogue via per-warp float scratch carved from As
    float* scr = (float*)smh + warp * 16 * 20;
#pragma unroll
    for (int i = 0; i < 4; i++) {
#pragma unroll
        for (int j = 0; j < 4; j++) {
            wmma::store_matrix_sync(scr, acc[i][j], 20, wmma::mem_row_major);
            __syncwarp();
#pragma unroll
            for (int e = 0; e < 8; e++) {
                int idx = lane + e * 32;
                int rr = idx >> 4, cc = idx & 15;
                int m = bm + wm * 64 + i * 16 + rr;
                int n = bn + wn * 64 + j * 16 + cc;
                float val = scr[rr * 20 + cc] + bias[n];
                if (EPI == 0) {
                    int which = n >> 10;           // 0=q 1=k 2=v
                    int hn = n & (H_ - 1);
                    int h  = hn >> 6;
                    int d  = hn & (HD_ - 1);
                    int bb = m >> 11;
                    int s  = m & (S_ - 1);
                    if (which == 0) val *= ATTN_SCALE;
                    size_t dst = ((size_t)(bb * NH_ + h) * S_ + s) * HD_ + d;
                    __half* T = (which == 0) ? g_q : (which == 1) ? g_k : g_v;
                    T[dst] = __float2half_rn(val);
                } else {
                    C[(size_t)m * N + n] = val;
                }
            }
            __syncwarp();
        }
    }
}

// ---------------- fp16 wmma attention (mask: allow j >= i) -------------------
// 64x64 tiles, 8 warps: wr=warp>>1 (16 rows), wc=warp&1 (32 cols).
// S accumulated fp32 -> float buffer; fused mask+exp+half-convert+rowsum pass
// writes half P buffer; QK/PV each 4 k16-steps. 3 block syncs per tile.
#define LDS_KV 80                         // 64 + 16 pad halves (160B rows)
#define KV_STAGE_H (64 * LDS_KV)          // 5120 halves
#define LDS_SF 72                         // float S buffer stride (288B rows)
#define SF_FLOATS (64 * LDS_SF)           // 4608 floats
#define PH_HALVES (64 * LDS_KV)           // 5120 halves
#define ATTN_SMEM (4 * KV_STAGE_H * 2 + SF_FLOATS * 4 + PH_HALVES * 2 + 256)

__global__ __launch_bounds__(256) void attn_fp16_kernel()
{
    extern __shared__ __half smh[];
    __half* Ks = smh;                              // [2][64][LDS_KV]
    __half* Vs = smh + 2 * KV_STAGE_H;             // [2][64][LDS_KV]
    float*  Sf = (float*)(smh + 4 * KV_STAGE_H);   // [64][LDS_SF]
    __half* Ph = (__half*)(Sf + SF_FLOATS);        // [64][LDS_KV]  (Q staging, then P)
    float*  l_s = (float*)(Ph + PH_HALVES);        // [64]

    const int qt = blockIdx.x;
    const int bh = blockIdx.y;
    const __half* Qb = g_q + (size_t)bh * S_ * HD_;
    const __half* Kb = g_k + (size_t)bh * S_ * HD_;
    const __half* Vb = g_v + (size_t)bh * S_ * HD_;

    const int tid  = threadIdx.x;
    const int warp = tid >> 5;
    const int wr   = warp >> 1;
    const int wc   = warp & 1;

    auto load_kv = [&](int st, int kt) {
        // 64 rows x 64 halves = 512 x 16B chunks each for K and V
#pragma unroll
        for (int it = 0; it < 2; it++) {
            int idx = tid + it * 256;
            int r   = idx >> 3;
            int c8  = (idx & 7) << 3;
            size_t src = (size_t)(kt * 64 + r) * HD_ + c8;
            CP_ASYNC16(smem_u32(&Ks[st * KV_STAGE_H + r * LDS_KV + c8]), &Kb[src]);
            CP_ASYNC16(smem_u32(&Vs[st * KV_STAGE_H + r * LDS_KV + c8]), &Vb[src]);
        }
    };

    const int nkt = S_ / 64 - qt;
    load_kv(0, qt);
    CP_COMMIT();

    // stage Q (half, pre-scaled) into Ph
#pragma unroll
    for (int it = 0; it < 2; it++) {
        int idx = tid + it * 256;
        int r   = idx >> 3;
        int c8  = (idx & 7) << 3;
        *reinterpret_cast<uint4*>(&Ph[r * LDS_KV + c8]) =
            *reinterpret_cast<const uint4*>(&Qb[(size_t)(qt * 64 + r) * HD_ + c8]);
    }
    if (tid < 64) l_s[tid] = 0.0f;
    __syncthreads();

    wmma::fragment<wmma::matrix_a, 16, 16, 16, __half, wmma::row_major> qf[4];
#pragma unroll
    for (int kk = 0; kk < 4; kk++)
        wmma::load_matrix_sync(qf[kk], &Ph[(wr * 16) * LDS_KV + kk * 16], LDS_KV);

    wmma::fragment<wmma::accumulator, 16, 16, 16, float> o_acc[2];
    wmma::fill_fragment(o_acc[0], 0.0f);
    wmma::fill_fragment(o_acc[1], 0.0f);
    // first in-loop sync [A] orders qf loads (all warps) before Ph is reused for P

    for (int i = 0; i < nkt; i++) {
        const int kt = qt + i;
        CP_WAIT(0);
        __syncthreads();                    // [A] KV stage i visible; other slot free
        if (i + 1 < nkt) {
            load_kv((i + 1) & 1, kt + 1);   // overlaps this tile's compute
            CP_COMMIT();
        }
        const __half* Kc = &Ks[(i & 1) * KV_STAGE_H];
        const __half* Vc = &Vs[(i & 1) * KV_STAGE_H];

        // S = Q @ K^T  (fp16 in, fp32 accum)
        wmma::fragment<wmma::accumulator, 16, 16, 16, float> s_acc[2];
        wmma::fill_fragment(s_acc[0], 0.0f);
        wmma::fill_fragment(s_acc[1], 0.0f);
#pragma unroll
        for (int kk = 0; kk < 4; kk++) {
            wmma::fragment<wmma::matrix_b, 16, 16, 16, __half, wmma::col_major> kf[2];
#pragma unroll
            for (int j = 0; j < 2; j++)
                wmma::load_matrix_sync(kf[j], &Kc[(wc * 32 + j * 16) * LDS_KV + kk * 16], LDS_KV);
            wmma::mma_sync(s_acc[0], qf[kk], kf[0], s_acc[0]);
            wmma::mma_sync(s_acc[1], qf[kk], kf[1], s_acc[1]);
        }
        wmma::store_matrix_sync(&Sf[(wr * 16) * LDS_SF + wc * 32],      s_acc[0], LDS_SF, wmma::mem_row_major);
        wmma::store_matrix_sync(&Sf[(wr * 16) * LDS_SF + wc * 32 + 16], s_acc[1], LDS_SF, wmma::mem_row_major);
        __syncthreads();                    // [B] S visible

        // fused mask + exp + half-convert + row-sum  (mask is trivially true off-diagonal)
        {
            int row  = tid >> 2;
            int col0 = (tid & 3) << 4;
            int grow = qt * 64 + row;
            int gc0  = kt * 64 + col0;
            float part = 0.0f;
#pragma unroll
            for (int c = 0; c < 16; c++) {
                float s = Sf[row * LDS_SF + col0 + c];
                float p = (gc0 + c >= grow) ? __expf(s) : 0.0f;
                __half hp = __float2half_rn(p);
                Ph[row * LDS_KV + col0 + c] = hp;
                part += __half2float(hp);
            }
            part += __shfl_xor_sync(0xffffffffu, part, 1);
            part += __shfl_xor_sync(0xffffffffu, part, 2);
            if ((tid & 3) == 0) l_s[row] += part;
        }
        __syncthreads();                    // [C] P visible to PV mma

        // O += P @ V
#pragma unroll
        for (int kk = 0; kk < 4; kk++) {
            wmma::fragment<wmma::matrix_a, 16, 16, 16, __half, wmma::row_major> pf;
            wmma::load_matrix_sync(pf, &Ph[(wr * 16) * LDS_KV + kk * 16], LDS_KV);
            wmma::fragment<wmma::matrix_b, 16, 16, 16, __half, wmma::row_major> vf[2];
#pragma unroll
            for (int j = 0; j < 2; j++)
                wmma::load_matrix_sync(vf[j], &Vc[(kk * 16) * LDS_KV + wc * 32 + j * 16], LDS_KV);
            wmma::mma_sync(o_acc[0], pf, vf[0], o_acc[0]);
            wmma::mma_sync(o_acc[1], pf, vf[1], o_acc[1]);
        }
        // no tail sync: next iteration's [A] (or final barrier) covers Ph/Sf reuse
    }
    __syncthreads();   // all PV reads done before Sf reused for O staging

    wmma::store_matrix_sync(&Sf[(wr * 16) * LDS_SF + wc * 32],      o_acc[0], LDS_SF, wmma::mem_row_major);
    wmma::store_matrix_sync(&Sf[(wr * 16) * LDS_SF + wc * 32 + 16], o_acc[1], LDS_SF, wmma::mem_row_major);
    __syncthreads();
    {
        int row  = tid >> 2;
        int col0 = (tid & 3) << 4;
        int grow = qt * 64 + row;
        int bb = bh >> 4, h = bh & 15;
        float inv_l = 1.0f / l_s[row];
        size_t base = ((size_t)bb * S_ + grow) * H_ + h * HD_ + col0;
#pragma unroll
        for (int c = 0; c < 16; c++)
            g_att[base + c] = __float2half_rn(Sf[row * LDS_SF + col0 + c] * inv_l);
    }
}

// ---------------- launch -----------------------------------------------------
extern "C" void kernel_launch(void* const* d_in, const int* in_sizes, int n_in,
                              void* d_out, int out_size)
{
    const float* x     = (const float*)d_in[0];
    const float* w_qkv = (const float*)d_in[1];
    const float* b_qkv = (const float*)d_in[2];
    const float* w_out = (const float*)d_in[3];
    const float* b_out = (const float*)d_in[4];
    float* out = (float*)d_out;

    cudaFuncSetAttribute(gemm_fp16_kernel<0>,
                         cudaFuncAttributeMaxDynamicSharedMemorySize, GEMM_SMEM);
    cudaFuncSetAttribute(gemm_fp16_kernel<1>,
                         cudaFuncAttributeMaxDynamicSharedMemorySize, GEMM_SMEM);
    cudaFuncSetAttribute(attn_fp16_kernel,
                         cudaFuncAttributeMaxDynamicSharedMemorySize, ATTN_SMEM);

    tohalf_all_kernel<<<(N4_TOTAL + 255) / 256, 256>>>(
        (const float4*)x, (const float4*)w_qkv, (const float4*)w_out);

    dim3 g1((3 * H_) / BN, MR_ / BM);
    gemm_fp16_kernel<0><<<g1, 128, GEMM_SMEM>>>(b_qkv, nullptr, MR_, 3 * H_, H_);

    dim3 g2(S_ / 64, B_ * NH_);
    attn_fp16_kernel<<<g2, 256, ATTN_SMEM>>>();

    dim3 g3(H_ / BN, MR_ / BM);
    gemm_fp16_kernel<1><<<g3, 128, GEMM_SMEM>>>(b_out, out, MR_, H_, H_);
}

// round 12
// speedup vs baseline: 2.2909x; 1.0013x over previous
#include <cuda_runtime.h>
#include <cuda_fp16.h>
#include <mma.h>
#include <math.h>
#include <cstdint>

using namespace nvcuda;

#define B_   2
#define S_   2048
#define H_   1024
#define NH_  16
#define HD_  64
#define MR_  (B_ * S_)
#define ATTN_SCALE 0.125f

// ---------------- scratch (half everywhere on the MMA paths) -----------------
__device__ __half g_x_h[MR_ * H_];           // fp16 x            [M][K]
__device__ __half g_wqkv_h[H_ * 3 * H_];     // fp16 w_qkv        [K][N]
__device__ __half g_wout_h[H_ * H_];         // fp16 w_out        [K][N]
__device__ __half g_q[B_ * NH_ * S_ * HD_];  // (b,h,s,d) q pre-scaled
__device__ __half g_k[B_ * NH_ * S_ * HD_];
__device__ __half g_v[B_ * NH_ * S_ * HD_];
__device__ __half g_att[MR_ * H_];           // (b,s,H)

// ---------------- cp.async helpers ------------------------------------------
__device__ __forceinline__ unsigned smem_u32(const void* p) {
    return (unsigned)__cvta_generic_to_shared(p);
}
#define CP_ASYNC16(dst_u32, src_ptr) \
    asm volatile("cp.async.cg.shared.global [%0], [%1], 16;\n" :: "r"(dst_u32), "l"(src_ptr))
#define CP_COMMIT() asm volatile("cp.async.commit_group;\n" ::)
#define CP_WAIT(N)  asm volatile("cp.async.wait_group %0;\n" :: "n"(N))
// pair-local named barrier: 64 threads (warps 2p, 2p+1), ids 1..4
#define PAIR_BAR(p) asm volatile("bar.sync %0, 64;" :: "r"(1 + (p)) : "memory")

// ---------------- prep: fused fp32 -> fp16 conversion ------------------------
#define N4_X  (MR_ * H_ / 4)
#define N4_WQ (H_ * 3 * H_ / 4)
#define N4_WO (H_ * H_ / 4)
#define N4_TOTAL (N4_X + N4_WQ + N4_WO)

__global__ void tohalf_all_kernel(const float4* __restrict__ x,
                                  const float4* __restrict__ wqkv,
                                  const float4* __restrict__ wout)
{
    int i = blockIdx.x * blockDim.x + threadIdx.x;
    const float4* src;
    __half2* dst;
    int j;
    if (i < N4_X)              { src = x;    dst = (__half2*)g_x_h;    j = i; }
    else if (i < N4_X + N4_WQ) { src = wqkv; dst = (__half2*)g_wqkv_h; j = i - N4_X; }
    else if (i < N4_TOTAL)     { src = wout; dst = (__half2*)g_wout_h; j = i - N4_X - N4_WQ; }
    else return;
    float4 v = src[j];
    dst[2 * j]     = __floats2half2_rn(v.x, v.y);
    dst[2 * j + 1] = __floats2half2_rn(v.z, v.w);
}

// ---------------- fp16 wmma GEMM: 4 warps, 64x64 warp tiles (unchanged) ------
#define BM 128
#define BN 128
#define BK 32
#define LDA_H 48
#define LDB_H 144
#define A_STAGE_H (BM * LDA_H)
#define B_STAGE_H (BK * LDB_H)
#define GEMM_SMEM ((2 * A_STAGE_H + 2 * B_STAGE_H) * 2)

template <int EPI>
__global__ __launch_bounds__(128) void gemm_fp16_kernel(
    const float* __restrict__ bias, float* __restrict__ C,
    int M, int N, int K)
{
    const __half* A  = (EPI == 1) ? (const __half*)g_att    : (const __half*)g_x_h;
    const __half* Bw = (EPI == 1) ? (const __half*)g_wout_h : (const __half*)g_wqkv_h;

    extern __shared__ __half smh[];
    __half* As = smh;
    __half* Bs = smh + 2 * A_STAGE_H;

    const int bm   = blockIdx.y * BM;
    const int bn   = blockIdx.x * BN;
    const int tid  = threadIdx.x;
    const int warp = tid >> 5;
    const int lane = tid & 31;
    const int wm   = warp >> 1;
    const int wn   = warp & 1;

    wmma::fragment<wmma::accumulator, 16, 16, 16, float> acc[4][4];
#pragma unroll
    for (int i = 0; i < 4; i++)
#pragma unroll
        for (int j = 0; j < 4; j++) wmma::fill_fragment(acc[i][j], 0.0f);

    const int NIT = K / BK;

    auto load_stage = [&](int st, int k0) {
#pragma unroll
        for (int it = 0; it < 4; it++) {
            int idx = tid + it * 128;
            int r   = idx >> 2;
            int c8  = (idx & 3) << 3;
            CP_ASYNC16(smem_u32(&As[st * A_STAGE_H + r * LDA_H + c8]),
                       &A[(size_t)(bm + r) * K + k0 + c8]);
        }
#pragma unroll
        for (int it = 0; it < 4; it++) {
            int idx = tid + it * 128;
            int r   = idx >> 4;
            int c8  = (idx & 15) << 3;
            CP_ASYNC16(smem_u32(&Bs[st * B_STAGE_H + r * LDB_H + c8]),
                       &Bw[(size_t)(k0 + r) * N + bn + c8]);
        }
    };

    load_stage(0, 0);
    CP_COMMIT();

    for (int it = 0; it < NIT; it++) {
        if (it + 1 < NIT) {
            load_stage((it + 1) & 1, (it + 1) * BK);
            CP_COMMIT();
            CP_WAIT(1);
        } else {
            CP_WAIT(0);
        }
        __syncthreads();

        const __half* Ac = &As[(it & 1) * A_STAGE_H];
        const __half* Bc = &Bs[(it & 1) * B_STAGE_H];
#pragma unroll
        for (int kk = 0; kk < BK / 16; kk++) {
            wmma::fragment<wmma::matrix_a, 16, 16, 16, __half, wmma::row_major> af[4];
            wmma::fragment<wmma::matrix_b, 16, 16, 16, __half, wmma::row_major> bf[4];
#pragma unroll
            for (int i = 0; i < 4; i++)
                wmma::load_matrix_sync(af[i], &Ac[(wm * 64 + i * 16) * LDA_H + kk * 16], LDA_H);
#pragma unroll
            for (int j = 0; j < 4; j++)
                wmma::load_matrix_sync(bf[j], &Bc[(kk * 16) * LDB_H + wn * 64 + j * 16], LDB_H);
#pragma unroll
            for (int i = 0; i < 4; i++)
#pragma unroll
                for (int j = 0; j < 4; j++)
                    wmma::mma_sync(acc[i][j], af[i], bf[j], acc[i][j]);
        }
        __syncthreads();
    }

    float* scr = (float*)smh + warp * 16 * 20;
#pragma unroll
    for (int i = 0; i < 4; i++) {
#pragma unroll
        for (int j = 0; j < 4; j++) {
            wmma::store_matrix_sync(scr, acc[i][j], 20, wmma::mem_row_major);
            __syncwarp();
#pragma unroll
            for (int e = 0; e < 8; e++) {
                int idx = lane + e * 32;
                int rr = idx >> 4, cc = idx & 15;
                int m = bm + wm * 64 + i * 16 + rr;
                int n = bn + wn * 64 + j * 16 + cc;
                float val = scr[rr * 20 + cc] + bias[n];
                if (EPI == 0) {
                    int which = n >> 10;           // 0=q 1=k 2=v
                    int hn = n & (H_ - 1);
                    int h  = hn >> 6;
                    int d  = hn & (HD_ - 1);
                    int bb = m >> 11;
                    int s  = m & (S_ - 1);
                    if (which == 0) val *= ATTN_SCALE;
                    size_t dst = ((size_t)(bb * NH_ + h) * S_ + s) * HD_ + d;
                    __half* T = (which == 0) ? g_q : (which == 1) ? g_k : g_v;
                    T[dst] = __float2half_rn(val);
                } else {
                    C[(size_t)m * N + n] = val;
                }
            }
            __syncwarp();
        }
    }
}

// ---------------- fp16 wmma attention (mask: allow j >= i) -------------------
// 64x64 tiles, 8 warps; warp pair p = warp>>1 owns S/P rows p*16..p*16+16.
// [A] stays block-wide (KV double-buffer guard). [B]/[C] become pair-local
// 64-thread named barriers: S rows are produced and consumed only within the
// pair, and cross-pair hazards (KV slots, Ph/Sf reuse across tiles) are
// ordered by [A]. Arithmetic identical to R11 -> rel_err unchanged.
#define LDS_KV 80
#define KV_STAGE_H (64 * LDS_KV)
#define LDS_SF 72
#define SF_FLOATS (64 * LDS_SF)
#define PH_HALVES (64 * LDS_KV)
#define ATTN_SMEM (4 * KV_STAGE_H * 2 + SF_FLOATS * 4 + PH_HALVES * 2 + 256)

__global__ __launch_bounds__(256) void attn_fp16_kernel()
{
    extern __shared__ __half smh[];
    __half* Ks = smh;                              // [2][64][LDS_KV]
    __half* Vs = smh + 2 * KV_STAGE_H;             // [2][64][LDS_KV]
    float*  Sf = (float*)(smh + 4 * KV_STAGE_H);   // [64][LDS_SF]
    __half* Ph = (__half*)(Sf + SF_FLOATS);        // [64][LDS_KV]
    float*  l_s = (float*)(Ph + PH_HALVES);        // [64]

    const int qt = blockIdx.x;
    const int bh = blockIdx.y;
    const __half* Qb = g_q + (size_t)bh * S_ * HD_;
    const __half* Kb = g_k + (size_t)bh * S_ * HD_;
    const __half* Vb = g_v + (size_t)bh * S_ * HD_;

    const int tid  = threadIdx.x;
    const int warp = tid >> 5;
    const int wr   = warp >> 1;          // pair id 0..3 (rows wr*16..+16)
    const int wc   = warp & 1;           // col half 0/1
    const int pt   = tid & 63;           // thread index within pair
    const int prow = wr * 16 + (pt >> 2);        // this thread's S/P row
    const int pcol0 = (pt & 3) << 4;             // 16-col chunk base

    auto load_kv = [&](int st, int kt) {
#pragma unroll
        for (int it = 0; it < 2; it++) {
            int idx = tid + it * 256;
            int r   = idx >> 3;
            int c8  = (idx & 7) << 3;
            size_t src = (size_t)(kt * 64 + r) * HD_ + c8;
            CP_ASYNC16(smem_u32(&Ks[st * KV_STAGE_H + r * LDS_KV + c8]), &Kb[src]);
            CP_ASYNC16(smem_u32(&Vs[st * KV_STAGE_H + r * LDS_KV + c8]), &Vb[src]);
        }
    };

    const int nkt = S_ / 64 - qt;
    load_kv(0, qt);
    CP_COMMIT();

    // stage Q (half, pre-scaled) into Ph
#pragma unroll
    for (int it = 0; it < 2; it++) {
        int idx = tid + it * 256;
        int r   = idx >> 3;
        int c8  = (idx & 7) << 3;
        *reinterpret_cast<uint4*>(&Ph[r * LDS_KV + c8]) =
            *reinterpret_cast<const uint4*>(&Qb[(size_t)(qt * 64 + r) * HD_ + c8]);
    }
    if (tid < 64) l_s[tid] = 0.0f;
    __syncthreads();

    wmma::fragment<wmma::matrix_a, 16, 16, 16, __half, wmma::row_major> qf[4];
#pragma unroll
    for (int kk = 0; kk < 4; kk++)
        wmma::load_matrix_sync(qf[kk], &Ph[(wr * 16) * LDS_KV + kk * 16], LDS_KV);

    wmma::fragment<wmma::accumulator, 16, 16, 16, float> o_acc[2];
    wmma::fill_fragment(o_acc[0], 0.0f);
    wmma::fill_fragment(o_acc[1], 0.0f);
    // first in-loop [A] (block-wide) orders qf loads before Ph is reused for P

    for (int i = 0; i < nkt; i++) {
        const int kt = qt + i;
        CP_WAIT(0);
        __syncthreads();                    // [A] block-wide: KV stage i visible
        if (i + 1 < nkt) {
            load_kv((i + 1) & 1, kt + 1);   // overlaps this tile's compute
            CP_COMMIT();
        }
        const __half* Kc = &Ks[(i & 1) * KV_STAGE_H];
        const __half* Vc = &Vs[(i & 1) * KV_STAGE_H];

        // S = Q @ K^T  (fp16 in, fp32 accum)
        wmma::fragment<wmma::accumulator, 16, 16, 16, float> s_acc[2];
        wmma::fill_fragment(s_acc[0], 0.0f);
        wmma::fill_fragment(s_acc[1], 0.0f);
#pragma unroll
        for (int kk = 0; kk < 4; kk++) {
            wmma::fragment<wmma::matrix_b, 16, 16, 16, __half, wmma::col_major> kf[2];
#pragma unroll
            for (int j = 0; j < 2; j++)
                wmma::load_matrix_sync(kf[j], &Kc[(wc * 32 + j * 16) * LDS_KV + kk * 16], LDS_KV);
            wmma::mma_sync(s_acc[0], qf[kk], kf[0], s_acc[0]);
            wmma::mma_sync(s_acc[1], qf[kk], kf[1], s_acc[1]);
        }
        wmma::store_matrix_sync(&Sf[(wr * 16) * LDS_SF + wc * 32],      s_acc[0], LDS_SF, wmma::mem_row_major);
        wmma::store_matrix_sync(&Sf[(wr * 16) * LDS_SF + wc * 32 + 16], s_acc[1], LDS_SF, wmma::mem_row_major);
        PAIR_BAR(wr);                       // [B] pair-local: S rows wr*16..+16 visible

        // fused mask + exp + half-convert + row-sum over the pair's own rows
        {
            int grow = qt * 64 + prow;
            int gc0  = kt * 64 + pcol0;
            float part = 0.0f;
#pragma unroll
            for (int c = 0; c < 16; c++) {
                float s = Sf[prow * LDS_SF + pcol0 + c];
                float p = (gc0 + c >= grow) ? __expf(s) : 0.0f;
                __half hp = __float2half_rn(p);
                Ph[prow * LDS_KV + pcol0 + c] = hp;
                part += __half2float(hp);
            }
            part += __shfl_xor_sync(0xffffffffu, part, 1);
            part += __shfl_xor_sync(0xffffffffu, part, 2);
            if ((pt & 3) == 0) l_s[prow] += part;
        }
        PAIR_BAR(wr);                       // [C] pair-local: P rows visible to pair's PV

        // O += P @ V  (pf reads only this pair's 16 rows of P)
#pragma unroll
        for (int kk = 0; kk < 4; kk++) {
            wmma::fragment<wmma::matrix_a, 16, 16, 16, __half, wmma::row_major> pf;
            wmma::load_matrix_sync(pf, &Ph[(wr * 16) * LDS_KV + kk * 16], LDS_KV);
            wmma::fragment<wmma::matrix_b, 16, 16, 16, __half, wmma::row_major> vf[2];
#pragma unroll
            for (int j = 0; j < 2; j++)
                wmma::load_matrix_sync(vf[j], &Vc[(kk * 16) * LDS_KV + wc * 32 + j * 16], LDS_KV);
            wmma::mma_sync(o_acc[0], pf, vf[0], o_acc[0]);
            wmma::mma_sync(o_acc[1], pf, vf[1], o_acc[1]);
        }
        // no tail sync: next iteration's [A] (block-wide) covers cross-tile reuse
    }
    __syncthreads();   // all PV reads done before Sf reused for O staging

    wmma::store_matrix_sync(&Sf[(wr * 16) * LDS_SF + wc * 32],      o_acc[0], LDS_SF, wmma::mem_row_major);
    wmma::store_matrix_sync(&Sf[(wr * 16) * LDS_SF + wc * 32 + 16], o_acc[1], LDS_SF, wmma::mem_row_major);
    __syncthreads();
    {
        int row  = tid >> 2;
        int col0 = (tid & 3) << 4;
        int grow = qt * 64 + row;
        int bb = bh >> 4, h = bh & 15;
        float inv_l = 1.0f / l_s[row];
        size_t base = ((size_t)bb * S_ + grow) * H_ + h * HD_ + col0;
#pragma unroll
        for (int c = 0; c < 16; c++)
            g_att[base + c] = __float2half_rn(Sf[row * LDS_SF + col0 + c] * inv_l);
    }
}

// ---------------- launch -----------------------------------------------------
extern "C" void kernel_launch(void* const* d_in, const int* in_sizes, int n_in,
                              void* d_out, int out_size)
{
    const float* x     = (const float*)d_in[0];
    const float* w_qkv = (const float*)d_in[1];
    const float* b_qkv = (const float*)d_in[2];
    const float* w_out = (const float*)d_in[3];
    const float* b_out = (const float*)d_in[4];
    float* out = (float*)d_out;

    cudaFuncSetAttribute(gemm_fp16_kernel<0>,
                         cudaFuncAttributeMaxDynamicSharedMemorySize, GEMM_SMEM);
    cudaFuncSetAttribute(gemm_fp16_kernel<1>,
                         cudaFuncAttributeMaxDynamicSharedMemorySize, GEMM_SMEM);
    cudaFuncSetAttribute(attn_fp16_kernel,
                         cudaFuncAttributeMaxDynamicSharedMemorySize, ATTN_SMEM);

    tohalf_all_kernel<<<(N4_TOTAL + 255) / 256, 256>>>(
        (const float4*)x, (const float4*)w_qkv, (const float4*)w_out);

    dim3 g1((3 * H_) / BN, MR_ / BM);
    gemm_fp16_kernel<0><<<g1, 128, GEMM_SMEM>>>(b_qkv, nullptr, MR_, 3 * H_, H_);

    dim3 g2(S_ / 64, B_ * NH_);
    attn_fp16_kernel<<<g2, 256, ATTN_SMEM>>>();

    dim3 g3(H_ / BN, MR_ / BM);
    gemm_fp16_kernel<1><<<g3, 128, GEMM_SMEM>>>(b_out, out, MR_, H_, H_);
}

// round 13
// speedup vs baseline: 3.3390x; 1.4575x over previous
#include <cuda_runtime.h>
#include <cuda_fp16.h>
#include <mma.h>
#include <math.h>
#include <cstdint>

using namespace nvcuda;

#define B_   2
#define S_   2048
#define H_   1024
#define NH_  16
#define HD_  64
#define MR_  (B_ * S_)
#define ATTN_SCALE 0.125f

// ---------------- scratch (half everywhere on the MMA paths) -----------------
__device__ __half g_x_h[MR_ * H_];           // fp16 x            [M][K]
__device__ __half g_wqkv_h[H_ * 3 * H_];     // fp16 w_qkv        [K][N]
__device__ __half g_wout_h[H_ * H_];         // fp16 w_out        [K][N]
__device__ __half g_q[B_ * NH_ * S_ * HD_];  // (b,h,s,d) q pre-scaled
__device__ __half g_k[B_ * NH_ * S_ * HD_];
__device__ __half g_v[B_ * NH_ * S_ * HD_];
__device__ __half g_att[MR_ * H_];           // (b,s,H)

// ---------------- cp.async helpers ------------------------------------------
__device__ __forceinline__ unsigned smem_u32(const void* p) {
    return (unsigned)__cvta_generic_to_shared(p);
}
#define CP_ASYNC16(dst_u32, src_ptr) \
    asm volatile("cp.async.cg.shared.global [%0], [%1], 16;\n" :: "r"(dst_u32), "l"(src_ptr))
#define CP_COMMIT() asm volatile("cp.async.commit_group;\n" ::)
#define CP_WAIT(N)  asm volatile("cp.async.wait_group %0;\n" :: "n"(N))
// pair-local named barrier: 64 threads (warps 2p, 2p+1), ids 1..4
#define PAIR_BAR(p) asm volatile("bar.sync %0, 64;" :: "r"(1 + (p)) : "memory")

// ---------------- prep: fused fp32 -> fp16 conversion ------------------------
#define N4_X  (MR_ * H_ / 4)
#define N4_WQ (H_ * 3 * H_ / 4)
#define N4_WO (H_ * H_ / 4)
#define N4_TOTAL (N4_X + N4_WQ + N4_WO)

__global__ void tohalf_all_kernel(const float4* __restrict__ x,
                                  const float4* __restrict__ wqkv,
                                  const float4* __restrict__ wout)
{
    int i = blockIdx.x * blockDim.x + threadIdx.x;
    const float4* src;
    __half2* dst;
    int j;
    if (i < N4_X)              { src = x;    dst = (__half2*)g_x_h;    j = i; }
    else if (i < N4_X + N4_WQ) { src = wqkv; dst = (__half2*)g_wqkv_h; j = i - N4_X; }
    else if (i < N4_TOTAL)     { src = wout; dst = (__half2*)g_wout_h; j = i - N4_X - N4_WQ; }
    else return;
    float4 v = src[j];
    dst[2 * j]     = __floats2half2_rn(v.x, v.y);
    dst[2 * j + 1] = __floats2half2_rn(v.z, v.w);
}

// ---------------- fp16 wmma GEMM: 4 warps, 64x64 warp tiles (unchanged) ------
#define BM 128
#define BN 128
#define BK 32
#define LDA_H 48
#define LDB_H 144
#define A_STAGE_H (BM * LDA_H)
#define B_STAGE_H (BK * LDB_H)
#define GEMM_SMEM ((2 * A_STAGE_H + 2 * B_STAGE_H) * 2)

template <int EPI>
__global__ __launch_bounds__(128) void gemm_fp16_kernel(
    const float* __restrict__ bias, float* __restrict__ C,
    int M, int N, int K)
{
    const __half* A  = (EPI == 1) ? (const __half*)g_att    : (const __half*)g_x_h;
    const __half* Bw = (EPI == 1) ? (const __half*)g_wout_h : (const __half*)g_wqkv_h;

    extern __shared__ __half smh[];
    __half* As = smh;
    __half* Bs = smh + 2 * A_STAGE_H;

    const int bm   = blockIdx.y * BM;
    const int bn   = blockIdx.x * BN;
    const int tid  = threadIdx.x;
    const int warp = tid >> 5;
    const int lane = tid & 31;
    const int wm   = warp >> 1;
    const int wn   = warp & 1;

    wmma::fragment<wmma::accumulator, 16, 16, 16, float> acc[4][4];
#pragma unroll
    for (int i = 0; i < 4; i++)
#pragma unroll
        for (int j = 0; j < 4; j++) wmma::fill_fragment(acc[i][j], 0.0f);

    const int NIT = K / BK;

    auto load_stage = [&](int st, int k0) {
#pragma unroll
        for (int it = 0; it < 4; it++) {
            int idx = tid + it * 128;
            int r   = idx >> 2;
            int c8  = (idx & 3) << 3;
            CP_ASYNC16(smem_u32(&As[st * A_STAGE_H + r * LDA_H + c8]),
                       &A[(size_t)(bm + r) * K + k0 + c8]);
        }
#pragma unroll
        for (int it = 0; it < 4; it++) {
            int idx = tid + it * 128;
            int r   = idx >> 4;
            int c8  = (idx & 15) << 3;
            CP_ASYNC16(smem_u32(&Bs[st * B_STAGE_H + r * LDB_H + c8]),
                       &Bw[(size_t)(k0 + r) * N + bn + c8]);
        }
    };

    load_stage(0, 0);
    CP_COMMIT();

    for (int it = 0; it < NIT; it++) {
        if (it + 1 < NIT) {
            load_stage((it + 1) & 1, (it + 1) * BK);
            CP_COMMIT();
            CP_WAIT(1);
        } else {
            CP_WAIT(0);
        }
        __syncthreads();

        const __half* Ac = &As[(it & 1) * A_STAGE_H];
        const __half* Bc = &Bs[(it & 1) * B_STAGE_H];
#pragma unroll
        for (int kk = 0; kk < BK / 16; kk++) {
            wmma::fragment<wmma::matrix_a, 16, 16, 16, __half, wmma::row_major> af[4];
            wmma::fragment<wmma::matrix_b, 16, 16, 16, __half, wmma::row_major> bf[4];
#pragma unroll
            for (int i = 0; i < 4; i++)
                wmma::load_matrix_sync(af[i], &Ac[(wm * 64 + i * 16) * LDA_H + kk * 16], LDA_H);
#pragma unroll
            for (int j = 0; j < 4; j++)
                wmma::load_matrix_sync(bf[j], &Bc[(kk * 16) * LDB_H + wn * 64 + j * 16], LDB_H);
#pragma unroll
            for (int i = 0; i < 4; i++)
#pragma unroll
                for (int j = 0; j < 4; j++)
                    wmma::mma_sync(acc[i][j], af[i], bf[j], acc[i][j]);
        }
        __syncthreads();
    }

    float* scr = (float*)smh + warp * 16 * 20;
#pragma unroll
    for (int i = 0; i < 4; i++) {
#pragma unroll
        for (int j = 0; j < 4; j++) {
            wmma::store_matrix_sync(scr, acc[i][j], 20, wmma::mem_row_major);
            __syncwarp();
#pragma unroll
            for (int e = 0; e < 8; e++) {
                int idx = lane + e * 32;
                int rr = idx >> 4, cc = idx & 15;
                int m = bm + wm * 64 + i * 16 + rr;
                int n = bn + wn * 64 + j * 16 + cc;
                float val = scr[rr * 20 + cc] + bias[n];
                if (EPI == 0) {
                    int which = n >> 10;           // 0=q 1=k 2=v
                    int hn = n & (H_ - 1);
                    int h  = hn >> 6;
                    int d  = hn & (HD_ - 1);
                    int bb = m >> 11;
                    int s  = m & (S_ - 1);
                    if (which == 0) val *= ATTN_SCALE;
                    size_t dst = ((size_t)(bb * NH_ + h) * S_ + s) * HD_ + d;
                    __half* T = (which == 0) ? g_q : (which == 1) ? g_k : g_v;
                    T[dst] = __float2half_rn(val);
                } else {
                    C[(size_t)m * N + n] = val;
                }
            }
            __syncwarp();
        }
    }
}

// ---------------- fp16 wmma attention (mask: allow j >= i) -------------------
// 64x64 tiles, 8 warps; pair p=warp>>1 owns S/P rows p*16..+16, wc=col half.
// NEW: exp applied IN-REGISTER on the fp32 score fragments, converted
// elementwise into half accumulator fragments, stored once as fp16 P.
// The fp32 Sf buffer, its store+reload pass, and one barrier per off-diagonal
// tile are gone. Flow (off-diag): QK -> reg exp/cvt -> P store -> PAIR_BAR ->
// {row-sum read || PV}. Diagonal tile: pass zeroes masked P entries (+1 bar).
#define LDS_KV 80
#define KV_STAGE_H (64 * LDS_KV)
#define PH_HALVES (64 * LDS_KV)
#define LDS_OF 72
#define ATTN_SMEM (4 * KV_STAGE_H * 2 + PH_HALVES * 2 + 256)   // ~51.2 KB

__global__ __launch_bounds__(256) void attn_fp16_kernel()
{
    extern __shared__ __half smh[];
    __half* Ks = smh;                              // [2][64][LDS_KV]
    __half* Vs = smh + 2 * KV_STAGE_H;             // [2][64][LDS_KV]
    __half* Ph = smh + 4 * KV_STAGE_H;             // [64][LDS_KV] (Q staging, then P)
    float*  l_s = (float*)(Ph + PH_HALVES);        // [64]
    float*  Of  = (float*)Ks;                      // O staging after loop (Ks dead)

    const int qt = blockIdx.x;
    const int bh = blockIdx.y;
    const __half* Qb = g_q + (size_t)bh * S_ * HD_;
    const __half* Kb = g_k + (size_t)bh * S_ * HD_;
    const __half* Vb = g_v + (size_t)bh * S_ * HD_;

    const int tid  = threadIdx.x;
    const int warp = tid >> 5;
    const int wr   = warp >> 1;          // pair id 0..3 (rows wr*16..+16)
    const int wc   = warp & 1;           // col half 0/1
    const int pt   = tid & 63;           // thread index within pair
    const int prow = wr * 16 + (pt >> 2);        // this thread's P row
    const int pcol0 = (pt & 3) << 4;             // 16-col chunk base

    auto load_kv = [&](int st, int kt) {
#pragma unroll
        for (int it = 0; it < 2; it++) {
            int idx = tid + it * 256;
            int r   = idx >> 3;
            int c8  = (idx & 7) << 3;
            size_t src = (size_t)(kt * 64 + r) * HD_ + c8;
            CP_ASYNC16(smem_u32(&Ks[st * KV_STAGE_H + r * LDS_KV + c8]), &Kb[src]);
            CP_ASYNC16(smem_u32(&Vs[st * KV_STAGE_H + r * LDS_KV + c8]), &Vb[src]);
        }
    };

    const int nkt = S_ / 64 - qt;
    load_kv(0, qt);
    CP_COMMIT();

    // stage Q (half, pre-scaled) into Ph
#pragma unroll
    for (int it = 0; it < 2; it++) {
        int idx = tid + it * 256;
        int r   = idx >> 3;
        int c8  = (idx & 7) << 3;
        *reinterpret_cast<uint4*>(&Ph[r * LDS_KV + c8]) =
            *reinterpret_cast<const uint4*>(&Qb[(size_t)(qt * 64 + r) * HD_ + c8]);
    }
    if (tid < 64) l_s[tid] = 0.0f;
    __syncthreads();

    wmma::fragment<wmma::matrix_a, 16, 16, 16, __half, wmma::row_major> qf[4];
#pragma unroll
    for (int kk = 0; kk < 4; kk++)
        wmma::load_matrix_sync(qf[kk], &Ph[(wr * 16) * LDS_KV + kk * 16], LDS_KV);

    wmma::fragment<wmma::accumulator, 16, 16, 16, float> o_acc[2];
    wmma::fill_fragment(o_acc[0], 0.0f);
    wmma::fill_fragment(o_acc[1], 0.0f);
    // first in-loop [A] (block-wide) orders qf loads before Ph is reused for P

    for (int i = 0; i < nkt; i++) {
        const int kt = qt + i;
        CP_WAIT(0);
        __syncthreads();                    // [A] block-wide: KV stage i visible
        if (i + 1 < nkt) {
            load_kv((i + 1) & 1, kt + 1);   // overlaps this tile's compute
            CP_COMMIT();
        }
        const __half* Kc = &Ks[(i & 1) * KV_STAGE_H];
        const __half* Vc = &Vs[(i & 1) * KV_STAGE_H];

        // S = Q @ K^T  (fp16 in, fp32 accum)
        wmma::fragment<wmma::accumulator, 16, 16, 16, float> s_acc[2];
        wmma::fill_fragment(s_acc[0], 0.0f);
        wmma::fill_fragment(s_acc[1], 0.0f);
#pragma unroll
        for (int kk = 0; kk < 4; kk++) {
            wmma::fragment<wmma::matrix_b, 16, 16, 16, __half, wmma::col_major> kf[2];
#pragma unroll
            for (int j = 0; j < 2; j++)
                wmma::load_matrix_sync(kf[j], &Kc[(wc * 32 + j * 16) * LDS_KV + kk * 16], LDS_KV);
            wmma::mma_sync(s_acc[0], qf[kk], kf[0], s_acc[0]);
            wmma::mma_sync(s_acc[1], qf[kk], kf[1], s_acc[1]);
        }

        // exp + fp16 convert IN REGISTER (elementwise; float/half accumulator
        // fragments of equal shape share per-thread element mapping)
        wmma::fragment<wmma::accumulator, 16, 16, 16, __half> p_h[2];
#pragma unroll
        for (int t = 0; t < s_acc[0].num_elements; t++) {
            p_h[0].x[t] = __float2half_rn(__expf(s_acc[0].x[t]));
            p_h[1].x[t] = __float2half_rn(__expf(s_acc[1].x[t]));
        }
        wmma::store_matrix_sync(&Ph[(wr * 16) * LDS_KV + wc * 32],      p_h[0], LDS_KV, wmma::mem_row_major);
        wmma::store_matrix_sync(&Ph[(wr * 16) * LDS_KV + wc * 32 + 16], p_h[1], LDS_KV, wmma::mem_row_major);
        PAIR_BAR(wr);                       // [B] pair-local: P rows visible

        if (i == 0) {
            // diagonal tile: zero masked entries, then row sums (+1 bar)
            int grow = qt * 64 + prow;
            int gc0  = kt * 64 + pcol0;
            float part = 0.0f;
#pragma unroll
            for (int c = 0; c < 16; c++) {
                __half hp = Ph[prow * LDS_KV + pcol0 + c];
                if (gc0 + c < grow) {
                    hp = __float2half_rn(0.0f);
                    Ph[prow * LDS_KV + pcol0 + c] = hp;
                }
                part += __half2float(hp);
            }
            part += __shfl_xor_sync(0xffffffffu, part, 1);
            part += __shfl_xor_sync(0xffffffffu, part, 2);
            if ((pt & 3) == 0) l_s[prow] += part;
            PAIR_BAR(wr);                   // masked P visible before PV
        } else {
            // row sums: read-only on P (concurrent with PV fragment loads)
            float part = 0.0f;
            const __half2* prow_p = (const __half2*)&Ph[prow * LDS_KV + pcol0];
#pragma unroll
            for (int c = 0; c < 8; c++) {
                float2 f = __half22float2(prow_p[c]);
                part += f.x + f.y;
            }
            part += __shfl_xor_sync(0xffffffffu, part, 1);
            part += __shfl_xor_sync(0xffffffffu, part, 2);
            if ((pt & 3) == 0) l_s[prow] += part;
            // no bar: PV below also only reads Ph; next write ordered by [A]
        }

        // O += P @ V  (pf reads this pair's 16 rows of P)
#pragma unroll
        for (int kk = 0; kk < 4; kk++) {
            wmma::fragment<wmma::matrix_a, 16, 16, 16, __half, wmma::row_major> pf;
            wmma::load_matrix_sync(pf, &Ph[(wr * 16) * LDS_KV + kk * 16], LDS_KV);
            wmma::fragment<wmma::matrix_b, 16, 16, 16, __half, wmma::row_major> vf[2];
#pragma unroll
            for (int j = 0; j < 2; j++)
                wmma::load_matrix_sync(vf[j], &Vc[(kk * 16) * LDS_KV + wc * 32 + j * 16], LDS_KV);
            wmma::mma_sync(o_acc[0], pf, vf[0], o_acc[0]);
            wmma::mma_sync(o_acc[1], pf, vf[1], o_acc[1]);
        }
        // no tail sync: next iteration's [A] (block-wide) covers reuse
    }
    __syncthreads();   // loop done; Ks region is dead -> reuse as float O staging

    wmma::store_matrix_sync(&Of[(wr * 16) * LDS_OF + wc * 32],      o_acc[0], LDS_OF, wmma::mem_row_major);
    wmma::store_matrix_sync(&Of[(wr * 16) * LDS_OF + wc * 32 + 16], o_acc[1], LDS_OF, wmma::mem_row_major);
    __syncthreads();
    {
        int row  = tid >> 2;
        int col0 = (tid & 3) << 4;
        int grow = qt * 64 + row;
        int bb = bh >> 4, h = bh & 15;
        float inv_l = 1.0f / l_s[row];
        size_t base = ((size_t)bb * S_ + grow) * H_ + h * HD_ + col0;
#pragma unroll
        for (int c = 0; c < 16; c++)
            g_att[base + c] = __float2half_rn(Of[row * LDS_OF + col0 + c] * inv_l);
    }
}

// ---------------- launch -----------------------------------------------------
extern "C" void kernel_launch(void* const* d_in, const int* in_sizes, int n_in,
                              void* d_out, int out_size)
{
    const float* x     = (const float*)d_in[0];
    const float* w_qkv = (const float*)d_in[1];
    const float* b_qkv = (const float*)d_in[2];
    const float* w_out = (const float*)d_in[3];
    const float* b_out = (const float*)d_in[4];
    float* out = (float*)d_out;

    cudaFuncSetAttribute(gemm_fp16_kernel<0>,
                         cudaFuncAttributeMaxDynamicSharedMemorySize, GEMM_SMEM);
    cudaFuncSetAttribute(gemm_fp16_kernel<1>,
                         cudaFuncAttributeMaxDynamicSharedMemorySize, GEMM_SMEM);
    cudaFuncSetAttribute(attn_fp16_kernel,
                         cudaFuncAttributeMaxDynamicSharedMemorySize, ATTN_SMEM);

    tohalf_all_kernel<<<(N4_TOTAL + 255) / 256, 256>>>(
        (const float4*)x, (const float4*)w_qkv, (const float4*)w_out);

    dim3 g1((3 * H_) / BN, MR_ / BM);
    gemm_fp16_kernel<0><<<g1, 128, GEMM_SMEM>>>(b_qkv, nullptr, MR_, 3 * H_, H_);

    dim3 g2(S_ / 64, B_ * NH_);
    attn_fp16_kernel<<<g2, 256, ATTN_SMEM>>>();

    dim3 g3(H_ / BN, MR_ / BM);
    gemm_fp16_kernel<1><<<g3, 128, GEMM_SMEM>>>(b_out, out, MR_, H_, H_);
}

// round 15
// speedup vs baseline: 3.3893x; 1.0151x over previous
#include <cuda_runtime.h>
#include <cuda_fp16.h>
#include <mma.h>
#include <math.h>
#include <cstdint>

using namespace nvcuda;

#define B_   2
#define S_   2048
#define H_   1024
#define NH_  16
#define HD_  64
#define MR_  (B_ * S_)
#define ATTN_SCALE 0.125f

// ---------------- scratch (half everywhere on the MMA paths) -----------------
__device__ __half g_x_h[MR_ * H_];           // fp16 x            [M][K]
__device__ __half g_wqkv_h[H_ * 3 * H_];     // fp16 w_qkv        [K][N]
__device__ __half g_wout_h[H_ * H_];         // fp16 w_out        [K][N]
__device__ __half g_q[B_ * NH_ * S_ * HD_];  // (b,h,s,d) q pre-scaled
__device__ __half g_k[B_ * NH_ * S_ * HD_];
__device__ __half g_v[B_ * NH_ * S_ * HD_];
__device__ __half g_att[MR_ * H_];           // (b,s,H)

// ---------------- cp.async helpers ------------------------------------------
__device__ __forceinline__ unsigned smem_u32(const void* p) {
    return (unsigned)__cvta_generic_to_shared(p);
}
#define CP_ASYNC16(dst_u32, src_ptr) \
    asm volatile("cp.async.cg.shared.global [%0], [%1], 16;\n" :: "r"(dst_u32), "l"(src_ptr))
#define CP_COMMIT() asm volatile("cp.async.commit_group;\n" ::)
#define CP_WAIT(N)  asm volatile("cp.async.wait_group %0;\n" :: "n"(N))
// pair-local named barrier: 64 threads (warps 2p, 2p+1), ids 1..4
#define PAIR_BAR(p) asm volatile("bar.sync %0, 64;" :: "r"(1 + (p)) : "memory")

// ---------------- prep: fused fp32 -> fp16 conversion ------------------------
#define N4_X  (MR_ * H_ / 4)
#define N4_WQ (H_ * 3 * H_ / 4)
#define N4_WO (H_ * H_ / 4)
#define N4_TOTAL (N4_X + N4_WQ + N4_WO)

__global__ void tohalf_all_kernel(const float4* __restrict__ x,
                                  const float4* __restrict__ wqkv,
                                  const float4* __restrict__ wout)
{
    int i = blockIdx.x * blockDim.x + threadIdx.x;
    const float4* src;
    __half2* dst;
    int j;
    if (i < N4_X)              { src = x;    dst = (__half2*)g_x_h;    j = i; }
    else if (i < N4_X + N4_WQ) { src = wqkv; dst = (__half2*)g_wqkv_h; j = i - N4_X; }
    else if (i < N4_TOTAL)     { src = wout; dst = (__half2*)g_wout_h; j = i - N4_X - N4_WQ; }
    else return;
    float4 v = src[j];
    dst[2 * j]     = __floats2half2_rn(v.x, v.y);
    dst[2 * j + 1] = __floats2half2_rn(v.z, v.w);
}

// ---------------- fp16 wmma GEMM: 4 warps, 64x64 warp tiles, BK=64 -----------
// BM=BN=128, BK=64 (4 k16-steps per barrier window), 128 threads (2x2 warps).
// Halves barrier count vs BK=32; 76KB smem -> 2 CTAs/SM (8 warps, above the
// 4-warp cliff from R7). Same R4-style 2-sync schedule.
#define BM 128
#define BN 128
#define BK 64
#define LDA_H 80     // 64 + 16 pad halves (160B rows)
#define LDB_H 144    // 128 + 16 pad halves
#define A_STAGE_H (BM * LDA_H)     // 10240 halves
#define B_STAGE_H (BK * LDB_H)     // 9216 halves
#define GEMM_SMEM ((2 * A_STAGE_H + 2 * B_STAGE_H) * 2)   // 77824 B

template <int EPI>
__global__ __launch_bounds__(128) void gemm_fp16_kernel(
    const float* __restrict__ bias, float* __restrict__ C,
    int M, int N, int K)
{
    const __half* A  = (EPI == 1) ? (const __half*)g_att    : (const __half*)g_x_h;
    const __half* Bw = (EPI == 1) ? (const __half*)g_wout_h : (const __half*)g_wqkv_h;

    extern __shared__ __half smh[];
    __half* As = smh;
    __half* Bs = smh + 2 * A_STAGE_H;

    const int bm   = blockIdx.y * BM;
    const int bn   = blockIdx.x * BN;
    const int tid  = threadIdx.x;
    const int warp = tid >> 5;
    const int lane = tid & 31;
    const int wm   = warp >> 1;
    const int wn   = warp & 1;

    wmma::fragment<wmma::accumulator, 16, 16, 16, float> acc[4][4];
#pragma unroll
    for (int i = 0; i < 4; i++)
#pragma unroll
        for (int j = 0; j < 4; j++) wmma::fill_fragment(acc[i][j], 0.0f);

    const int NIT = K / BK;    // 16

    auto load_stage = [&](int st, int k0) {
        // A: 128 rows x 64 halves = 1024 x 16B chunks
#pragma unroll
        for (int it = 0; it < 8; it++) {
            int idx = tid + it * 128;
            int r   = idx >> 3;
            int c8  = (idx & 7) << 3;
            CP_ASYNC16(smem_u32(&As[st * A_STAGE_H + r * LDA_H + c8]),
                       &A[(size_t)(bm + r) * K + k0 + c8]);
        }
        // B: 64 rows x 128 halves = 1024 x 16B chunks
#pragma unroll
        for (int it = 0; it < 8; it++) {
            int idx = tid + it * 128;
            int r   = idx >> 4;
            int c8  = (idx & 15) << 3;
            CP_ASYNC16(smem_u32(&Bs[st * B_STAGE_H + r * LDB_H + c8]),
                       &Bw[(size_t)(k0 + r) * N + bn + c8]);
        }
    };

    load_stage(0, 0);
    CP_COMMIT();

    for (int it = 0; it < NIT; it++) {
        if (it + 1 < NIT) {
            load_stage((it + 1) & 1, (it + 1) * BK);
            CP_COMMIT();
            CP_WAIT(1);
        } else {
            CP_WAIT(0);
        }
        __syncthreads();

        const __half* Ac = &As[(it & 1) * A_STAGE_H];
        const __half* Bc = &Bs[(it & 1) * B_STAGE_H];
#pragma unroll
        for (int kk = 0; kk < BK / 16; kk++) {
            wmma::fragment<wmma::matrix_a, 16, 16, 16, __half, wmma::row_major> af[4];
            wmma::fragment<wmma::matrix_b, 16, 16, 16, __half, wmma::row_major> bf[4];
#pragma unroll
            for (int i = 0; i < 4; i++)
                wmma::load_matrix_sync(af[i], &Ac[(wm * 64 + i * 16) * LDA_H + kk * 16], LDA_H);
#pragma unroll
            for (int j = 0; j < 4; j++)
                wmma::load_matrix_sync(bf[j], &Bc[(kk * 16) * LDB_H + wn * 64 + j * 16], LDB_H);
#pragma unroll
            for (int i = 0; i < 4; i++)
#pragma unroll
                for (int j = 0; j < 4; j++)
                    wmma::mma_sync(acc[i][j], af[i], bf[j], acc[i][j]);
        }
        __syncthreads();
    }

    float* scr = (float*)smh + warp * 16 * 20;
#pragma unroll
    for (int i = 0; i < 4; i++) {
#pragma unroll
        for (int j = 0; j < 4; j++) {
            wmma::store_matrix_sync(scr, acc[i][j], 20, wmma::mem_row_major);
            __syncwarp();
#pragma unroll
            for (int e = 0; e < 8; e++) {
                int idx = lane + e * 32;
                int rr = idx >> 4, cc = idx & 15;
                int m = bm + wm * 64 + i * 16 + rr;
                int n = bn + wn * 64 + j * 16 + cc;
                float val = scr[rr * 20 + cc] + bias[n];
                if (EPI == 0) {
                    int which = n >> 10;           // 0=q 1=k 2=v
                    int hn = n & (H_ - 1);
                    int h  = hn >> 6;
                    int d  = hn & (HD_ - 1);
                    int bb = m >> 11;
                    int s  = m & (S_ - 1);
                    if (which == 0) val *= ATTN_SCALE;
                    size_t dst = ((size_t)(bb * NH_ + h) * S_ + s) * HD_ + d;
                    __half* T = (which == 0) ? g_q : (which == 1) ? g_k : g_v;
                    T[dst] = __float2half_rn(val);
                } else {
                    C[(size_t)m * N + n] = val;
                }
            }
            __syncwarp();
        }
    }
}

// ---------------- fp16 wmma attention (unchanged from R13) -------------------
#define LDS_KV 80
#define KV_STAGE_H (64 * LDS_KV)
#define PH_HALVES (64 * LDS_KV)
#define LDS_OF 72
#define ATTN_SMEM (4 * KV_STAGE_H * 2 + PH_HALVES * 2 + 256)   // ~51.2 KB

__global__ __launch_bounds__(256) void attn_fp16_kernel()
{
    extern __shared__ __half smh[];
    __half* Ks = smh;                              // [2][64][LDS_KV]
    __half* Vs = smh + 2 * KV_STAGE_H;             // [2][64][LDS_KV]
    __half* Ph = smh + 4 * KV_STAGE_H;             // [64][LDS_KV] (Q staging, then P)
    float*  l_s = (float*)(Ph + PH_HALVES);        // [64]
    float*  Of  = (float*)Ks;                      // O staging after loop (Ks dead)

    const int qt = blockIdx.x;
    const int bh = blockIdx.y;
    const __half* Qb = g_q + (size_t)bh * S_ * HD_;
    const __half* Kb = g_k + (size_t)bh * S_ * HD_;
    const __half* Vb = g_v + (size_t)bh * S_ * HD_;

    const int tid  = threadIdx.x;
    const int warp = tid >> 5;
    const int wr   = warp >> 1;          // pair id 0..3 (rows wr*16..+16)
    const int wc   = warp & 1;           // col half 0/1
    const int pt   = tid & 63;           // thread index within pair
    const int prow = wr * 16 + (pt >> 2);        // this thread's P row
    const int pcol0 = (pt & 3) << 4;             // 16-col chunk base

    auto load_kv = [&](int st, int kt) {
#pragma unroll
        for (int it = 0; it < 2; it++) {
            int idx = tid + it * 256;
            int r   = idx >> 3;
            int c8  = (idx & 7) << 3;
            size_t src = (size_t)(kt * 64 + r) * HD_ + c8;
            CP_ASYNC16(smem_u32(&Ks[st * KV_STAGE_H + r * LDS_KV + c8]), &Kb[src]);
            CP_ASYNC16(smem_u32(&Vs[st * KV_STAGE_H + r * LDS_KV + c8]), &Vb[src]);
        }
    };

    const int nkt = S_ / 64 - qt;
    load_kv(0, qt);
    CP_COMMIT();

    // stage Q (half, pre-scaled) into Ph
#pragma unroll
    for (int it = 0; it < 2; it++) {
        int idx = tid + it * 256;
        int r   = idx >> 3;
        int c8  = (idx & 7) << 3;
        *reinterpret_cast<uint4*>(&Ph[r * LDS_KV + c8]) =
            *reinterpret_cast<const uint4*>(&Qb[(size_t)(qt * 64 + r) * HD_ + c8]);
    }
    if (tid < 64) l_s[tid] = 0.0f;
    __syncthreads();

    wmma::fragment<wmma::matrix_a, 16, 16, 16, __half, wmma::row_major> qf[4];
#pragma unroll
    for (int kk = 0; kk < 4; kk++)
        wmma::load_matrix_sync(qf[kk], &Ph[(wr * 16) * LDS_KV + kk * 16], LDS_KV);

    wmma::fragment<wmma::accumulator, 16, 16, 16, float> o_acc[2];
    wmma::fill_fragment(o_acc[0], 0.0f);
    wmma::fill_fragment(o_acc[1], 0.0f);
    // first in-loop [A] (block-wide) orders qf loads before Ph is reused for P

    for (int i = 0; i < nkt; i++) {
        const int kt = qt + i;
        CP_WAIT(0);
        __syncthreads();                    // [A] block-wide: KV stage i visible
        if (i + 1 < nkt) {
            load_kv((i + 1) & 1, kt + 1);   // overlaps this tile's compute
            CP_COMMIT();
        }
        const __half* Kc = &Ks[(i & 1) * KV_STAGE_H];
        const __half* Vc = &Vs[(i & 1) * KV_STAGE_H];

        // S = Q @ K^T  (fp16 in, fp32 accum)
        wmma::fragment<wmma::accumulator, 16, 16, 16, float> s_acc[2];
        wmma::fill_fragment(s_acc[0], 0.0f);
        wmma::fill_fragment(s_acc[1], 0.0f);
#pragma unroll
        for (int kk = 0; kk < 4; kk++) {
            wmma::fragment<wmma::matrix_b, 16, 16, 16, __half, wmma::col_major> kf[2];
#pragma unroll
            for (int j = 0; j < 2; j++)
                wmma::load_matrix_sync(kf[j], &Kc[(wc * 32 + j * 16) * LDS_KV + kk * 16], LDS_KV);
            wmma::mma_sync(s_acc[0], qf[kk], kf[0], s_acc[0]);
            wmma::mma_sync(s_acc[1], qf[kk], kf[1], s_acc[1]);
        }

        // exp + fp16 convert IN REGISTER
        wmma::fragment<wmma::accumulator, 16, 16, 16, __half> p_h[2];
#pragma unroll
        for (int t = 0; t < s_acc[0].num_elements; t++) {
            p_h[0].x[t] = __float2half_rn(__expf(s_acc[0].x[t]));
            p_h[1].x[t] = __float2half_rn(__expf(s_acc[1].x[t]));
        }
        wmma::store_matrix_sync(&Ph[(wr * 16) * LDS_KV + wc * 32],      p_h[0], LDS_KV, wmma::mem_row_major);
        wmma::store_matrix_sync(&Ph[(wr * 16) * LDS_KV + wc * 32 + 16], p_h[1], LDS_KV, wmma::mem_row_major);
        PAIR_BAR(wr);                       // [B] pair-local: P rows visible

        if (i == 0) {
            // diagonal tile: zero masked entries, then row sums (+1 bar)
            int grow = qt * 64 + prow;
            int gc0  = kt * 64 + pcol0;
            float part = 0.0f;
#pragma unroll
            for (int c = 0; c < 16; c++) {
                __half hp = Ph[prow * LDS_KV + pcol0 + c];
                if (gc0 + c < grow) {
                    hp = __float2half_rn(0.0f);
                    Ph[prow * LDS_KV + pcol0 + c] = hp;
                }
                part += __half2float(hp);
            }
            part += __shfl_xor_sync(0xffffffffu, part, 1);
            part += __shfl_xor_sync(0xffffffffu, part, 2);
            if ((pt & 3) == 0) l_s[prow] += part;
            PAIR_BAR(wr);                   // masked P visible before PV
        } else {
            // row sums: read-only on P (concurrent with PV fragment loads)
            float part = 0.0f;
            const __half2* prow_p = (const __half2*)&Ph[prow * LDS_KV + pcol0];
#pragma unroll
            for (int c = 0; c < 8; c++) {
                float2 f = __half22float2(prow_p[c]);
                part += f.x + f.y;
            }
            part += __shfl_xor_sync(0xffffffffu, part, 1);
            part += __shfl_xor_sync(0xffffffffu, part, 2);
            if ((pt & 3) == 0) l_s[prow] += part;
            // no bar: PV below also only reads Ph; next write ordered by [A]
        }

        // O += P @ V  (pf reads this pair's 16 rows of P)
#pragma unroll
        for (int kk = 0; kk < 4; kk++) {
            wmma::fragment<wmma::matrix_a, 16, 16, 16, __half, wmma::row_major> pf;
            wmma::load_matrix_sync(pf, &Ph[(wr * 16) * LDS_KV + kk * 16], LDS_KV);
            wmma::fragment<wmma::matrix_b, 16, 16, 16, __half, wmma::row_major> vf[2];
#pragma unroll
            for (int j = 0; j < 2; j++)
                wmma::load_matrix_sync(vf[j], &Vc[(kk * 16) * LDS_KV + wc * 32 + j * 16], LDS_KV);
            wmma::mma_sync(o_acc[0], pf, vf[0], o_acc[0]);
            wmma::mma_sync(o_acc[1], pf, vf[1], o_acc[1]);
        }
        // no tail sync: next iteration's [A] (block-wide) covers reuse
    }
    __syncthreads();   // loop done; Ks region is dead -> reuse as float O staging

    wmma::store_matrix_sync(&Of[(wr * 16) * LDS_OF + wc * 32],      o_acc[0], LDS_OF, wmma::mem_row_major);
    wmma::store_matrix_sync(&Of[(wr * 16) * LDS_OF + wc * 32 + 16], o_acc[1], LDS_OF, wmma::mem_row_major);
    __syncthreads();
    {
        int row  = tid >> 2;
        int col0 = (tid & 3) << 4;
        int grow = qt * 64 + row;
        int bb = bh >> 4, h = bh & 15;
        float inv_l = 1.0f / l_s[row];
        size_t base = ((size_t)bb * S_ + grow) * H_ + h * HD_ + col0;
#pragma unroll
        for (int c = 0; c < 16; c++)
            g_att[base + c] = __float2half_rn(Of[row * LDS_OF + col0 + c] * inv_l);
    }
}

// ---------------- launch -----------------------------------------------------
extern "C" void kernel_launch(void* const* d_in, const int* in_sizes, int n_in,
                              void* d_out, int out_size)
{
    const float* x     = (const float*)d_in[0];
    const float* w_qkv = (const float*)d_in[1];
    const float* b_qkv = (const float*)d_in[2];
    const float* w_out = (const float*)d_in[3];
    const float* b_out = (const float*)d_in[4];
    float* out = (float*)d_out;

    cudaFuncSetAttribute(gemm_fp16_kernel<0>,
                         cudaFuncAttributeMaxDynamicSharedMemorySize, GEMM_SMEM);
    cudaFuncSetAttribute(gemm_fp16_kernel<1>,
                         cudaFuncAttributeMaxDynamicSharedMemorySize, GEMM_SMEM);
    cudaFuncSetAttribute(attn_fp16_kernel,
                         cudaFuncAttributeMaxDynamicSharedMemorySize, ATTN_SMEM);

    tohalf_all_kernel<<<(N4_TOTAL + 255) / 256, 256>>>(
        (const float4*)x, (const float4*)w_qkv, (const float4*)w_out);

    dim3 g1((3 * H_) / BN, MR_ / BM);
    gemm_fp16_kernel<0><<<g1, 128, GEMM_SMEM>>>(b_qkv, nullptr, MR_, 3 * H_, H_);

    dim3 g2(S_ / 64, B_ * NH_);
    attn_fp16_kernel<<<g2, 256, ATTN_SMEM>>>();

    dim3 g3(H_ / BN, MR_ / BM);
    gemm_fp16_kernel<1><<<g3, 128, GEMM_SMEM>>>(b_out, out, MR_, H_, H_);
}